// round 14
// baseline (speedup 1.0000x reference)
#include <cuda_runtime.h>
#include <cuda_fp16.h>
#include <math.h>
#include <stdint.h>

// ---------------- problem constants ----------------
#define NS    16384
#define DIMX  3200
#define LMAX  4

__constant__ int c_offD[4] = {0, 9, 34, 83};

// 13 sub-GEMMs: 0: m0 (N=640, K=512); per m=1..4: A, B, A+B (co x co)
__constant__ int cg_tileStart[14] = {0,640,1152,1664,2176,2560,2944,3328,3584,3840,4096,4224,4352,4480};
__constant__ int cg_Ksub[13]  = {512,512,512,512,384,384,384,256,256,256,128,128,128};
__constant__ int cg_Nsub[13]  = {640,512,512,512,384,384,384,256,256,256,128,128,128};
__constant__ int cg_Up[13]    = {0,512,1024,1536,2048,2432,2816,3200,3456,3712,3968,4096,4224};
__constant__ int cg_Zp[13]    = {0,640,1152,1664,2176,2560,2944,3328,3584,3840,4096,4224,4352};
__constant__ int cg_Wpref[14] = {0,327680,589824,851968,1114112,1261568,1409024,1556480,1622016,1687552,1753088,1769472,1785856,1802240};

// ---------------- device scratch ----------------
__device__ float g_J[164];
__device__ __half g_W[1802240];
__device__ __half g_U[(size_t)NS * 4352];
__device__ __half g_Z[(size_t)NS * 4480];     // fp16 GEMM outputs

// =======================================================================
// Kernel 0: build J matrices (reference algorithm, fp64, parallel)
// =======================================================================
__global__ void build_J_kernel() {
    __shared__ double Xr[4][81], Xi[4][81], Qr[4][81], Qi[4][81];
    __shared__ double Sa[4][81], Se[4][81], St[4][81];
    int g = threadIdx.x / 96;
    int e = threadIdx.x % 96;
    int l = g + 1, d = 2*l + 1, dd = d*d;
    const double j = (double)l;
    const double SQ12 = 0.70710678118654752440;
    const double PI_D = 3.14159265358979323846;

    if (e < 81) { Xr[g][e]=0; Xi[g][e]=0; Qr[g][e]=0; Qi[g][e]=0; }
    __syncthreads();
    if (e == 0) {
        for (int i2 = 0; i2 < d-1; i2++) {
            double m  = -j + (double)i2;
            double rv = -sqrt(j*(j+1.0) - m*(m+1.0));
            Xr[g][(i2+1)*d + i2] += 0.5 * rv;
            double m2 = -j + 1.0 + (double)i2;
            double lv = sqrt(j*(j+1.0) - m2*(m2-1.0));
            Xr[g][i2*d + (i2+1)] += 0.5 * lv;
        }
        for (int i2 = 0; i2 < d; i2++) Xi[g][i2*d + i2] += (-j + (double)i2);
        for (int m = 1; m <= l; m++) {
            int r = l - m;
            Qr[g][r*d + (l+m)] = SQ12;
            Qi[g][r*d + r]     = -SQ12;
            int r2 = l + m;
            double sgn = (m & 1) ? -1.0 : 1.0;
            Qr[g][r2*d + r2]     = sgn * SQ12;
            Qi[g][r2*d + (l-m)]  = sgn * SQ12;
        }
        Qr[g][l*d + l] = 1.0;
    }
    __syncthreads();
    if (e < dd) {
        int i = e / d, jj = e % d;
        double s = 0.0;
        for (int k = 0; k < d; k++) {
            double mr = 0.0, mi = 0.0;
            for (int p = 0; p < d; p++) {
                mr += Xr[g][k*d+p]*Qr[g][p*d+jj] - Xi[g][k*d+p]*Qi[g][p*d+jj];
                mi += Xr[g][k*d+p]*Qi[g][p*d+jj] + Xi[g][k*d+p]*Qr[g][p*d+jj];
            }
            s += Qr[g][k*d+i]*mr + Qi[g][k*d+i]*mi;
        }
        Sa[g][e] = (PI_D * SQ12) * s * (1.0/1024.0);
        Se[g][e] = (i == jj) ? 1.0 : 0.0;
        St[g][e] = (i == jj) ? 1.0 : 0.0;
    }
    __syncthreads();
    for (int k = 1; k < 24; k++) {
        double v = 0.0;
        if (e < dd) {
            int i = e / d, jj = e % d;
            double s = 0.0;
            for (int p = 0; p < d; p++) s += St[g][i*d+p] * Sa[g][p*d+jj];
            v = s / (double)k;
        }
        __syncthreads();
        if (e < dd) { St[g][e] = v; Se[g][e] += v; }
        __syncthreads();
    }
    for (int s2 = 0; s2 < 10; s2++) {
        double v = 0.0;
        if (e < dd) {
            int i = e / d, jj = e % d;
            double s = 0.0;
            for (int p = 0; p < d; p++) s += Se[g][i*d+p] * Se[g][p*d+jj];
            v = s;
        }
        __syncthreads();
        if (e < dd) Se[g][e] = v;
        __syncthreads();
    }
    if (e < dd) g_J[c_offD[g] + e] = (float)Se[g][e];
}

// =======================================================================
// Kernel 1: build W (fp16): sub 0 = fc0_w cols 128..639; subs 3m-2..3m: A, B, A+B
// =======================================================================
__global__ void build_w_kernel(const float* __restrict__ fc0_w,
                               const float* __restrict__ w1, const float* __restrict__ w2,
                               const float* __restrict__ w3, const float* __restrict__ w4) {
    int gid = blockIdx.x * blockDim.x + threadIdx.x;
    if (gid >= 1802240) return;
    int s = 0;
    #pragma unroll
    for (int q = 1; q < 13; q++) if (gid >= cg_Wpref[q]) s = q;
    int local = gid - cg_Wpref[s];
    int K = cg_Ksub[s];
    int o = local / K;
    int t = local - o * K;
    float v;
    if (s == 0) {
        v = fc0_w[o * 640 + t + 128];
    } else {
        int m = (s - 1) / 3 + 1;
        int which = (s - 1) % 3;
        const float* w = (m == 1) ? w1 : (m == 2) ? w2 : (m == 3) ? w3 : w4;
        if (which == 0)      v = w[o * K + t];
        else if (which == 1) v = w[(K + o) * K + t];
        else                 v = w[o * K + t] + w[(K + o) * K + t];
    }
    g_W[gid] = __float2half_rn(v);
}

// =======================================================================
// In-CTA Wigner D^T: warps 0-3 compute l = wid+1 into dt[] (t1 scratch).
// =======================================================================
__device__ __forceinline__ void compute_DT_smem(int n, const float* __restrict__ R,
                                                float* dt, float* t1, int tid) {
    int wid = tid >> 5, lane = tid & 31;
    if (wid >= 4) return;
    int l = wid + 1, d = 2*l + 1, dd = d*d;

    float vx = R[n*3 + 1], vy = R[n*3 + 2], vz = R[n*3 + 0];
    float nrm = sqrtf(vx*vx + vy*vy + vz*vz);
    nrm = fmaxf(nrm, 1e-12f);
    vx /= nrm; vy /= nrm; vz /= nrm;
    vx = fminf(fmaxf(vx, -1.f), 1.f);
    vy = fminf(fmaxf(vy, -1.f), 1.f);
    vz = fminf(fmaxf(vz, -1.f), 1.f);
    float beta  = acosf(vy);
    float alpha = atan2f(vx, vz);

    const float* J = g_J + c_offD[l-1];
    float* T1 = t1 + c_offD[l-1];
    float* DD = dt + c_offD[l-1];

    for (int e = lane; e < dd; e += 32) {
        int i = e / d, jj = e - i * d;
        float fr = (float)(l - i);
        float c = cosf(fr * beta), s = sinf(fr * beta);
        T1[e] = c * J[e] + s * J[(d - 1 - i)*d + jj];
    }
    __syncwarp();
    for (int e = lane; e < dd; e += 32) {
        int i = e / d, jj = e - i * d;
        float s2 = 0.f;
        for (int k = 0; k < d; k++) s2 += J[i*d + k] * T1[k*d + jj];
        DD[e] = s2;
    }
    __syncwarp();
    float dv[3]; int cnt = 0;
    for (int e = lane; e < dd; e += 32) {
        int i = e / d, jj = e - i * d;
        float fr = (float)(l - i);
        float c = cosf(fr * alpha), s = sinf(fr * alpha);
        dv[cnt++] = c * DD[i*d + jj] + s * DD[(d - 1 - i)*d + jj];
    }
    __syncwarp();
    cnt = 0;
    for (int e = lane; e < dd; e += 32) {
        int i = e / d, jj = e - i * d;
        DD[jj*d + i] = dv[cnt++];
    }
}

// =======================================================================
// Kernel 3: rotate x in-place (block-per-thread), gather fp16 inputs (half2)
// =======================================================================
__global__ __launch_bounds__(256) void rot_gather_kernel(const float* __restrict__ x,
                                                         const float* __restrict__ R) {
    int n = blockIdx.x;
    __shared__ float xs[DIMX];
    __shared__ float dt[164];
    __shared__ float t1s[164];
    const float4* xr4 = (const float4*)(x + (size_t)n * DIMX);
    for (int c = threadIdx.x; c < DIMX/4; c += 256) ((float4*)xs)[c] = xr4[c];
    compute_DT_smem(n, R, dt, t1s, threadIdx.x);
    __syncthreads();

    int k = threadIdx.x & 127;
    int h = threadIdx.x >> 7;
    #define ROTBLK(D, DTO, XO) do {                                          \
        float* xb = xs + XO + k * D;                                         \
        float xv[D];                                                         \
        _Pragma("unroll") for (int j = 0; j < D; j++) xv[j] = xb[j];         \
        _Pragma("unroll") for (int i = 0; i < D; i++) {                      \
            const float* ddp = dt + DTO + i * D;                             \
            float v = 0.f;                                                   \
            _Pragma("unroll") for (int j = 0; j < D; j++) v += ddp[j] * xv[j]; \
            xb[i] = v;                                                       \
        }                                                                    \
    } while (0)
    if (h == 0) { ROTBLK(3, 0, 128);  ROTBLK(9, 83, 2048); }
    else        { ROTBLK(5, 9, 512);  ROTBLK(7, 34, 1152); }
    __syncthreads();

    {
        int j = threadIdx.x * 2;
        if (j < 512) {
            int jj = j + 128;
            int l = jj >> 7, kk = jj & 127;
            int d = 2*l + 1;
            float va = xs[128*l*l + kk*d + l];
            float vb = xs[128*l*l + (kk+1)*d + l];
            *(__half2*)&g_U[(size_t)n * 512 + j] = __floats2half2_rn(va, vb);
        }
    }
    #define GATH(MM, CO, P0, P1, P2)                                         \
    for (int tb = threadIdx.x * 2; tb < CO; tb += 512) {                     \
        int ph = tb >> 1;                                                    \
        int l0 = MM + (ph >> 7), k0 = ph & 127;                              \
        int p1 = (CO >> 1) + ph;                                             \
        int l1 = MM + (p1 >> 7), k1 = p1 & 127;                              \
        int b0 = 128*l0*l0 + k0*(2*l0 + 1);                                  \
        int b1 = 128*l1*l1 + k1*(2*l1 + 1);                                  \
        float u0a = xs[b0 + l0 - MM], u0b = xs[b0 + l0 + MM];                \
        float u1a = xs[b1 + l1 - MM], u1b = xs[b1 + l1 + MM];                \
        *(__half2*)&g_U[(size_t)NS * P0 + (size_t)n * CO + tb] = __floats2half2_rn(u0a, u0b); \
        *(__half2*)&g_U[(size_t)NS * P1 + (size_t)n * CO + tb] = __floats2half2_rn(u1a, u1b); \
        *(__half2*)&g_U[(size_t)NS * P2 + (size_t)n * CO + tb] = __floats2half2_rn(u0a + u1a, u0b + u1b); \
    }
    GATH(1, 512, 512, 1024, 1536)
    GATH(2, 384, 2048, 2432, 2816)
    GATH(3, 256, 3200, 3456, 3712)
    GATH(4, 128, 3968, 4096, 4224)
}

// =======================================================================
// Kernel 4: HMMA fp16 GEMM over 13 sub-GEMMs
//   128x128 CTA tile, 128 threads (4 warps of 64x64), 3-stage cp.async
// =======================================================================
__device__ __forceinline__ uint32_t smem_u32(const void* p) {
    uint32_t a;
    asm("{ .reg .u64 t; cvta.to.shared.u64 t, %1; cvt.u32.u64 %0, t; }" : "=r"(a) : "l"(p));
    return a;
}
#define CP_ASYNC16(dst, src) \
    asm volatile("cp.async.cg.shared.global [%0], [%1], 16;" :: "r"(dst), "l"(src) : "memory")
#define CP_COMMIT() asm volatile("cp.async.commit_group;" ::: "memory")
#define CP_WAIT1()  asm volatile("cp.async.wait_group 1;" ::: "memory")
#define CP_WAIT0()  asm volatile("cp.async.wait_group 0;" ::: "memory")
#define LDSM_X4(r0, r1, r2, r3, addr) \
    asm volatile("ldmatrix.sync.aligned.m8n8.x4.shared.b16 {%0,%1,%2,%3}, [%4];" \
                 : "=r"(r0), "=r"(r1), "=r"(r2), "=r"(r3) : "r"(addr))

__device__ __forceinline__ void hmma16816(float* c, const uint32_t* a, const uint32_t* b) {
    asm volatile(
        "mma.sync.aligned.m16n8k16.row.col.f32.f16.f16.f32 "
        "{%0,%1,%2,%3}, {%4,%5,%6,%7}, {%8,%9}, {%0,%1,%2,%3};"
        : "+f"(c[0]), "+f"(c[1]), "+f"(c[2]), "+f"(c[3])
        : "r"(a[0]), "r"(a[1]), "r"(a[2]), "r"(a[3]), "r"(b[0]), "r"(b[1]));
}

__global__ __launch_bounds__(128) void hmma_gemm_all_kernel() {
    extern __shared__ __align__(1024) char dsm[];
    uint32_t sbase = smem_u32(dsm);

    int tid = threadIdx.x;
    int wid = tid >> 5;
    int lane = tid & 31;

    // ---- tile decode ----
    int id = blockIdx.x;
    int s = 0;
    #pragma unroll
    for (int q = 1; q < 13; q++) if (id >= cg_tileStart[q]) s = q;
    int local = id - cg_tileStart[s];
    int K = cg_Ksub[s];
    int N = cg_Nsub[s];
    int gx = N >> 7;
    int bcolt = local % gx, browt = local / gx;
    int brow = browt << 7, bcol = bcolt << 7;

    const __half* A = g_U + (size_t)NS * cg_Up[s];
    const __half* B = g_W + cg_Wpref[s];
    __half* C = g_Z + (size_t)NS * cg_Zp[s];

    // ---- global->smem: 1 thread/row, 8x16B chunks ----
    const char* gA = (const char*)(A + (size_t)(brow + tid) * K);
    const char* gB = (const char*)(B + (size_t)(bcol + tid) * K);
    uint32_t sts[8];
    #pragma unroll
    for (int i = 0; i < 8; i++) {
        uint32_t off = (uint32_t)tid * 128u + (uint32_t)i * 16u;
        sts[i] = off ^ ((off >> 3) & 0x70);
    }

    // ---- per-warp compute layout: 64x64 warp tile (4 warps, 2x2) ----
    int wm = wid >> 1, wn = wid & 1;
    uint32_t a_row[4], a_rx[4];
    #pragma unroll
    for (int mt = 0; mt < 4; mt++) {
        int row = wm * 64 + mt * 16 + (lane & 15);
        a_row[mt] = (uint32_t)row * 128u;
        a_rx[mt] = (uint32_t)(row & 7) << 4;
    }
    uint32_t a_cb = ((lane >> 4) & 1) * 16u;
    int nloc = (lane & 7) + ((lane & 16) >> 1);
    uint32_t b_row[4], b_rx[4];
    #pragma unroll
    for (int nt4 = 0; nt4 < 4; nt4++) {
        int nrow = wn * 64 + nt4 * 16 + nloc;
        b_row[nt4] = (uint32_t)nrow * 128u;
        b_rx[nt4] = (uint32_t)(nrow & 7) << 4;
    }
    uint32_t b_cb = ((lane >> 3) & 1) * 16u;

    float acc[4][8][4];
    #pragma unroll
    for (int mt = 0; mt < 4; mt++)
        #pragma unroll
        for (int nt = 0; nt < 8; nt++)
            #pragma unroll
            for (int e = 0; e < 4; e++) acc[mt][nt][e] = 0.f;

    int NC = K >> 6;

    // prologue: chunks 0,1 into stages 0,1
    #pragma unroll
    for (int p = 0; p < 2; p++) {
        uint32_t aS = sbase + (uint32_t)p * 32768u;
        uint32_t bS = aS + 16384u;
        const char* Ap = gA + (size_t)p * 128;
        const char* Bp = gB + (size_t)p * 128;
        #pragma unroll
        for (int i = 0; i < 8; i++) {
            CP_ASYNC16(aS + sts[i], Ap + i * 16);
            CP_ASYNC16(bS + sts[i], Bp + i * 16);
        }
        CP_COMMIT();
    }

    for (int c = 0; c < NC; ++c) {
        if (c + 1 < NC) CP_WAIT1(); else CP_WAIT0();
        __syncthreads();
        if (c + 2 < NC) {
            int st = (c + 2) % 3;
            uint32_t aS = sbase + (uint32_t)st * 32768u;
            uint32_t bS = aS + 16384u;
            const char* Ap = gA + (size_t)(c + 2) * 128;
            const char* Bp = gB + (size_t)(c + 2) * 128;
            #pragma unroll
            for (int i = 0; i < 8; i++) {
                CP_ASYNC16(aS + sts[i], Ap + i * 16);
                CP_ASYNC16(bS + sts[i], Bp + i * 16);
            }
            CP_COMMIT();
        }
        int cst = c % 3;
        uint32_t aS = sbase + (uint32_t)cst * 32768u;
        uint32_t bS = aS + 16384u;
        #pragma unroll
        for (int kq = 0; kq < 4; kq++) {
            uint32_t kb = (uint32_t)kq * 32u;
            uint32_t afr[4][4];
            #pragma unroll
            for (int mt = 0; mt < 4; mt++)
                LDSM_X4(afr[mt][0], afr[mt][1], afr[mt][2], afr[mt][3],
                        aS + a_row[mt] + ((a_cb + kb) ^ a_rx[mt]));
            uint32_t bfr[4][4];
            #pragma unroll
            for (int nt4 = 0; nt4 < 4; nt4++)
                LDSM_X4(bfr[nt4][0], bfr[nt4][1], bfr[nt4][2], bfr[nt4][3],
                        bS + b_row[nt4] + ((b_cb + kb) ^ b_rx[nt4]));
            #pragma unroll
            for (int mt = 0; mt < 4; mt++)
                #pragma unroll
                for (int nt = 0; nt < 8; nt++)
                    hmma16816(acc[mt][nt], afr[mt], &bfr[nt >> 1][(nt & 1) * 2]);
        }
    }

    // epilogue: fp16 stores (C row stride = N)
    int g2 = lane >> 2, t2 = lane & 3;
    #pragma unroll
    for (int mt = 0; mt < 4; mt++) {
        #pragma unroll
        for (int nt = 0; nt < 8; nt++) {
            int row0 = brow + wm * 64 + mt * 16 + g2;
            int col = bcol + wn * 64 + nt * 8 + t2 * 2;
            __half2 h0 = __floats2half2_rn(acc[mt][nt][0], acc[mt][nt][1]);
            __half2 h1 = __floats2half2_rn(acc[mt][nt][2], acc[mt][nt][3]);
            *(__half2*)(C + (size_t)row0 * N + col) = h0;
            *(__half2*)(C + (size_t)(row0 + 8) * N + col) = h1;
        }
    }
}

// =======================================================================
// Kernel 5: combine fp16 Karatsuba outputs (+bias), rotate in place, write out
// =======================================================================
__global__ __launch_bounds__(256) void scatter_rot_kernel(const float* __restrict__ fc0_b,
                                                          const float* __restrict__ R,
                                                          float* __restrict__ out) {
    int n = blockIdx.x;
    __shared__ float pre[DIMX];
    __shared__ float dt[164];
    __shared__ float t1s[164];

    compute_DT_smem(n, R, dt, t1s, threadIdx.x);

    for (int j = threadIdx.x * 2; j < 640; j += 512) {
        __half2 hz = *(const __half2*)&g_Z[(size_t)n * 640 + j];
        int l = j >> 7, k = j & 127;
        int base = 128*l*l;
        int d = 2*l + 1;
        pre[base + k*d + l]       = __low2float(hz)  + fc0_b[j];
        pre[base + (k+1)*d + l]   = __high2float(hz) + fc0_b[j+1];
    }
    #define SCAT(MM, CO, P0, P1, P2)                                         \
    for (int tb = threadIdx.x * 2; tb < CO; tb += 512) {                     \
        __half2 h1 = *(const __half2*)&g_Z[(size_t)NS * P0 + (size_t)n * CO + tb]; \
        __half2 h2 = *(const __half2*)&g_Z[(size_t)NS * P1 + (size_t)n * CO + tb]; \
        __half2 h3 = *(const __half2*)&g_Z[(size_t)NS * P2 + (size_t)n * CO + tb]; \
        float v1a = __low2float(h1), v1b = __high2float(h1);                 \
        float v2a = __low2float(h2), v2b = __high2float(h2);                 \
        float v3a = __low2float(h3), v3b = __high2float(h3);                 \
        float rea = v1a - v2a, reb = v1b - v2b;                              \
        float ima = v3a - v1a - v2a, imb = v3b - v1b - v2b;                  \
        int ph = tb >> 1;                                                    \
        int p1 = (CO >> 1) + ph;                                             \
        int l0 = MM + (ph >> 7), k0 = ph & 127;                              \
        int l1 = MM + (p1 >> 7), k1 = p1 & 127;                              \
        int b0 = 128*l0*l0 + k0*(2*l0 + 1);                                  \
        int b1 = 128*l1*l1 + k1*(2*l1 + 1);                                  \
        pre[b0 + l0 - MM] = rea;                                             \
        pre[b0 + l0 + MM] = reb;                                             \
        pre[b1 + l1 - MM] = ima;                                             \
        pre[b1 + l1 + MM] = imb;                                             \
    }
    SCAT(1, 512, 640, 1152, 1664)
    SCAT(2, 384, 2176, 2560, 2944)
    SCAT(3, 256, 3328, 3584, 3840)
    SCAT(4, 128, 4096, 4224, 4352)
    __syncthreads();

    int k = threadIdx.x & 127;
    int h = threadIdx.x >> 7;
    #define ROTO(D, DTO, XO) do {                                            \
        float* pb = pre + XO + k * D;                                        \
        float xv[D];                                                         \
        _Pragma("unroll") for (int j = 0; j < D; j++) xv[j] = pb[j];         \
        _Pragma("unroll") for (int i = 0; i < D; i++) {                      \
            const float* ddp = dt + DTO + i * D;                             \
            float v = 0.f;                                                   \
            _Pragma("unroll") for (int j = 0; j < D; j++) v += ddp[j] * xv[j]; \
            pb[i] = v;                                                       \
        }                                                                    \
    } while (0)
    if (h == 0) { ROTO(3, 0, 128);  ROTO(9, 83, 2048); }
    else        { ROTO(5, 9, 512);  ROTO(7, 34, 1152); }
    __syncthreads();

    float4* orow4 = (float4*)(out + (size_t)n * DIMX);
    for (int c = threadIdx.x; c < DIMX/4; c += 256) orow4[c] = ((const float4*)pre)[c];
}

// =======================================================================
// launch
// =======================================================================
extern "C" void kernel_launch(void* const* d_in, const int* in_sizes, int n_in,
                              void* d_out, int out_size) {
    const float* x     = (const float*)d_in[0];
    const float* R     = (const float*)d_in[1];
    const float* fc0_w = (const float*)d_in[2];
    const float* fc0_b = (const float*)d_in[3];
    const float* w1    = (const float*)d_in[4];
    const float* w2    = (const float*)d_in[5];
    const float* w3    = (const float*)d_in[6];
    const float* w4    = (const float*)d_in[7];
    float* out = (float*)d_out;

    build_J_kernel<<<1, 384>>>();
    build_w_kernel<<<(1802240 + 255) / 256, 256>>>(fc0_w, w1, w2, w3, w4);
    rot_gather_kernel<<<NS, 256>>>(x, R);

    cudaFuncSetAttribute(hmma_gemm_all_kernel,
                         cudaFuncAttributeMaxDynamicSharedMemorySize, 98304);
    hmma_gemm_all_kernel<<<4480, 128, 98304>>>();

    scatter_rot_kernel<<<NS, 256>>>(fc0_b, R, out);
}

// round 15
// speedup vs baseline: 1.1891x; 1.1891x over previous
#include <cuda_runtime.h>
#include <cuda_fp16.h>
#include <math.h>
#include <stdint.h>

// ---------------- problem constants ----------------
#define NS    16384
#define DIMX  3200
#define LMAX  4

__constant__ int c_offD[4] = {0, 9, 34, 83};

// 13 sub-GEMMs: 0: m0 (N=640, K=512); per m=1..4: A, B, A+B (co x co)
__constant__ int cg_tileStart[14] = {0,640,1152,1664,2176,2560,2944,3328,3584,3840,4096,4224,4352,4480};
__constant__ int cg_Ksub[13]  = {512,512,512,512,384,384,384,256,256,256,128,128,128};
__constant__ int cg_Nsub[13]  = {640,512,512,512,384,384,384,256,256,256,128,128,128};
__constant__ int cg_Up[13]    = {0,512,1024,1536,2048,2432,2816,3200,3456,3712,3968,4096,4224};
__constant__ int cg_Zp[13]    = {0,640,1152,1664,2176,2560,2944,3328,3584,3840,4096,4224,4352};
__constant__ int cg_Wpref[14] = {0,327680,589824,851968,1114112,1261568,1409024,1556480,1622016,1687552,1753088,1769472,1785856,1802240};

// ---------------- device scratch ----------------
__device__ float g_J[164];
__device__ __half g_W[1802240];
__device__ __half g_U[(size_t)NS * 4352];
__device__ __half g_Z[(size_t)NS * 4480];     // fp16 GEMM outputs

// =======================================================================
// Kernel 0+1 merged: block 0 builds J (fp64); blocks >=1 build W (fp16)
// =======================================================================
__device__ void build_J_block() {
    __shared__ double Xr[4][81], Xi[4][81], Qr[4][81], Qi[4][81];
    __shared__ double Sa[4][81], Se[4][81], St[4][81];
    int g = threadIdx.x / 96;
    int e = threadIdx.x % 96;
    int l = g + 1, d = 2*l + 1, dd = d*d;
    const double j = (double)l;
    const double SQ12 = 0.70710678118654752440;
    const double PI_D = 3.14159265358979323846;

    if (e < 81) { Xr[g][e]=0; Xi[g][e]=0; Qr[g][e]=0; Qi[g][e]=0; }
    __syncthreads();
    if (e == 0) {
        for (int i2 = 0; i2 < d-1; i2++) {
            double m  = -j + (double)i2;
            double rv = -sqrt(j*(j+1.0) - m*(m+1.0));
            Xr[g][(i2+1)*d + i2] += 0.5 * rv;
            double m2 = -j + 1.0 + (double)i2;
            double lv = sqrt(j*(j+1.0) - m2*(m2-1.0));
            Xr[g][i2*d + (i2+1)] += 0.5 * lv;
        }
        for (int i2 = 0; i2 < d; i2++) Xi[g][i2*d + i2] += (-j + (double)i2);
        for (int m = 1; m <= l; m++) {
            int r = l - m;
            Qr[g][r*d + (l+m)] = SQ12;
            Qi[g][r*d + r]     = -SQ12;
            int r2 = l + m;
            double sgn = (m & 1) ? -1.0 : 1.0;
            Qr[g][r2*d + r2]     = sgn * SQ12;
            Qi[g][r2*d + (l-m)]  = sgn * SQ12;
        }
        Qr[g][l*d + l] = 1.0;
    }
    __syncthreads();
    if (e < dd) {
        int i = e / d, jj = e % d;
        double s = 0.0;
        for (int k = 0; k < d; k++) {
            double mr = 0.0, mi = 0.0;
            for (int p = 0; p < d; p++) {
                mr += Xr[g][k*d+p]*Qr[g][p*d+jj] - Xi[g][k*d+p]*Qi[g][p*d+jj];
                mi += Xr[g][k*d+p]*Qi[g][p*d+jj] + Xi[g][k*d+p]*Qr[g][p*d+jj];
            }
            s += Qr[g][k*d+i]*mr + Qi[g][k*d+i]*mi;
        }
        Sa[g][e] = (PI_D * SQ12) * s * (1.0/1024.0);
        Se[g][e] = (i == jj) ? 1.0 : 0.0;
        St[g][e] = (i == jj) ? 1.0 : 0.0;
    }
    __syncthreads();
    for (int k = 1; k < 24; k++) {
        double v = 0.0;
        if (e < dd) {
            int i = e / d, jj = e % d;
            double s = 0.0;
            for (int p = 0; p < d; p++) s += St[g][i*d+p] * Sa[g][p*d+jj];
            v = s / (double)k;
        }
        __syncthreads();
        if (e < dd) { St[g][e] = v; Se[g][e] += v; }
        __syncthreads();
    }
    for (int s2 = 0; s2 < 10; s2++) {
        double v = 0.0;
        if (e < dd) {
            int i = e / d, jj = e % d;
            double s = 0.0;
            for (int p = 0; p < d; p++) s += Se[g][i*d+p] * Se[g][p*d+jj];
            v = s;
        }
        __syncthreads();
        if (e < dd) Se[g][e] = v;
        __syncthreads();
    }
    if (e < dd) g_J[c_offD[g] + e] = (float)Se[g][e];
}

__global__ __launch_bounds__(384) void build_all_kernel(
        const float* __restrict__ fc0_w,
        const float* __restrict__ w1, const float* __restrict__ w2,
        const float* __restrict__ w3, const float* __restrict__ w4) {
    if (blockIdx.x == 0) {
        build_J_block();
        return;
    }
    int gid = (blockIdx.x - 1) * 384 + threadIdx.x;
    if (gid >= 1802240) return;
    int s = 0;
    #pragma unroll
    for (int q = 1; q < 13; q++) if (gid >= cg_Wpref[q]) s = q;
    int local = gid - cg_Wpref[s];
    int K = cg_Ksub[s];
    int o = local / K;
    int t = local - o * K;
    float v;
    if (s == 0) {
        v = fc0_w[o * 640 + t + 128];
    } else {
        int m = (s - 1) / 3 + 1;
        int which = (s - 1) % 3;
        const float* w = (m == 1) ? w1 : (m == 2) ? w2 : (m == 3) ? w3 : w4;
        if (which == 0)      v = w[o * K + t];
        else if (which == 1) v = w[(K + o) * K + t];
        else                 v = w[o * K + t] + w[(K + o) * K + t];
    }
    g_W[gid] = __float2half_rn(v);
}

// =======================================================================
// In-CTA Wigner D^T: warps 0-3 compute l = wid+1 into dt[] (t1 scratch).
// =======================================================================
__device__ __forceinline__ void compute_DT_smem(int n, const float* __restrict__ R,
                                                float* dt, float* t1, int tid) {
    int wid = tid >> 5, lane = tid & 31;
    if (wid >= 4) return;
    int l = wid + 1, d = 2*l + 1, dd = d*d;

    float vx = R[n*3 + 1], vy = R[n*3 + 2], vz = R[n*3 + 0];
    float nrm = sqrtf(vx*vx + vy*vy + vz*vz);
    nrm = fmaxf(nrm, 1e-12f);
    vx /= nrm; vy /= nrm; vz /= nrm;
    vx = fminf(fmaxf(vx, -1.f), 1.f);
    vy = fminf(fmaxf(vy, -1.f), 1.f);
    vz = fminf(fmaxf(vz, -1.f), 1.f);
    float beta  = acosf(vy);
    float alpha = atan2f(vx, vz);

    const float* J = g_J + c_offD[l-1];
    float* T1 = t1 + c_offD[l-1];
    float* DD = dt + c_offD[l-1];

    for (int e = lane; e < dd; e += 32) {
        int i = e / d, jj = e - i * d;
        float fr = (float)(l - i);
        float c = cosf(fr * beta), s = sinf(fr * beta);
        T1[e] = c * J[e] + s * J[(d - 1 - i)*d + jj];
    }
    __syncwarp();
    for (int e = lane; e < dd; e += 32) {
        int i = e / d, jj = e - i * d;
        float s2 = 0.f;
        for (int k = 0; k < d; k++) s2 += J[i*d + k] * T1[k*d + jj];
        DD[e] = s2;
    }
    __syncwarp();
    float dv[3]; int cnt = 0;
    for (int e = lane; e < dd; e += 32) {
        int i = e / d, jj = e - i * d;
        float fr = (float)(l - i);
        float c = cosf(fr * alpha), s = sinf(fr * alpha);
        dv[cnt++] = c * DD[i*d + jj] + s * DD[(d - 1 - i)*d + jj];
    }
    __syncwarp();
    cnt = 0;
    for (int e = lane; e < dd; e += 32) {
        int i = e / d, jj = e - i * d;
        DD[jj*d + i] = dv[cnt++];
    }
}

// =======================================================================
// Kernel 3: rotate x in-place (block-per-thread), gather fp16 inputs (half2)
// =======================================================================
__global__ __launch_bounds__(256) void rot_gather_kernel(const float* __restrict__ x,
                                                         const float* __restrict__ R) {
    int n = blockIdx.x;
    __shared__ float xs[DIMX];
    __shared__ float dt[164];
    __shared__ float t1s[164];
    const float4* xr4 = (const float4*)(x + (size_t)n * DIMX);
    for (int c = threadIdx.x; c < DIMX/4; c += 256) ((float4*)xs)[c] = xr4[c];
    compute_DT_smem(n, R, dt, t1s, threadIdx.x);
    __syncthreads();

    int k = threadIdx.x & 127;
    int h = threadIdx.x >> 7;
    #define ROTBLK(D, DTO, XO) do {                                          \
        float* xb = xs + XO + k * D;                                         \
        float xv[D];                                                         \
        _Pragma("unroll") for (int j = 0; j < D; j++) xv[j] = xb[j];         \
        _Pragma("unroll") for (int i = 0; i < D; i++) {                      \
            const float* ddp = dt + DTO + i * D;                             \
            float v = 0.f;                                                   \
            _Pragma("unroll") for (int j = 0; j < D; j++) v += ddp[j] * xv[j]; \
            xb[i] = v;                                                       \
        }                                                                    \
    } while (0)
    if (h == 0) { ROTBLK(3, 0, 128);  ROTBLK(9, 83, 2048); }
    else        { ROTBLK(5, 9, 512);  ROTBLK(7, 34, 1152); }
    __syncthreads();

    {
        int j = threadIdx.x * 2;
        if (j < 512) {
            int jj = j + 128;
            int l = jj >> 7, kk = jj & 127;
            int d = 2*l + 1;
            float va = xs[128*l*l + kk*d + l];
            float vb = xs[128*l*l + (kk+1)*d + l];
            *(__half2*)&g_U[(size_t)n * 512 + j] = __floats2half2_rn(va, vb);
        }
    }
    #define GATH(MM, CO, P0, P1, P2)                                         \
    for (int tb = threadIdx.x * 2; tb < CO; tb += 512) {                     \
        int ph = tb >> 1;                                                    \
        int l0 = MM + (ph >> 7), k0 = ph & 127;                              \
        int p1 = (CO >> 1) + ph;                                             \
        int l1 = MM + (p1 >> 7), k1 = p1 & 127;                              \
        int b0 = 128*l0*l0 + k0*(2*l0 + 1);                                  \
        int b1 = 128*l1*l1 + k1*(2*l1 + 1);                                  \
        float u0a = xs[b0 + l0 - MM], u0b = xs[b0 + l0 + MM];                \
        float u1a = xs[b1 + l1 - MM], u1b = xs[b1 + l1 + MM];                \
        *(__half2*)&g_U[(size_t)NS * P0 + (size_t)n * CO + tb] = __floats2half2_rn(u0a, u0b); \
        *(__half2*)&g_U[(size_t)NS * P1 + (size_t)n * CO + tb] = __floats2half2_rn(u1a, u1b); \
        *(__half2*)&g_U[(size_t)NS * P2 + (size_t)n * CO + tb] = __floats2half2_rn(u0a + u1a, u0b + u1b); \
    }
    GATH(1, 512, 512, 1024, 1536)
    GATH(2, 384, 2048, 2432, 2816)
    GATH(3, 256, 3200, 3456, 3712)
    GATH(4, 128, 3968, 4096, 4224)
}

// =======================================================================
// Kernel 4: HMMA fp16 GEMM over 13 sub-GEMMs
//   128x128 CTA tile, 256 threads (8 warps of 32x64), 3-stage cp.async
//   (proven round-13 configuration)
// =======================================================================
__device__ __forceinline__ uint32_t smem_u32(const void* p) {
    uint32_t a;
    asm("{ .reg .u64 t; cvta.to.shared.u64 t, %1; cvt.u32.u64 %0, t; }" : "=r"(a) : "l"(p));
    return a;
}
#define CP_ASYNC16(dst, src) \
    asm volatile("cp.async.cg.shared.global [%0], [%1], 16;" :: "r"(dst), "l"(src) : "memory")
#define CP_COMMIT() asm volatile("cp.async.commit_group;" ::: "memory")
#define CP_WAIT1()  asm volatile("cp.async.wait_group 1;" ::: "memory")
#define CP_WAIT0()  asm volatile("cp.async.wait_group 0;" ::: "memory")
#define LDSM_X4(r0, r1, r2, r3, addr) \
    asm volatile("ldmatrix.sync.aligned.m8n8.x4.shared.b16 {%0,%1,%2,%3}, [%4];" \
                 : "=r"(r0), "=r"(r1), "=r"(r2), "=r"(r3) : "r"(addr))

__device__ __forceinline__ void hmma16816(float* c, const uint32_t* a, const uint32_t* b) {
    asm volatile(
        "mma.sync.aligned.m16n8k16.row.col.f32.f16.f16.f32 "
        "{%0,%1,%2,%3}, {%4,%5,%6,%7}, {%8,%9}, {%0,%1,%2,%3};"
        : "+f"(c[0]), "+f"(c[1]), "+f"(c[2]), "+f"(c[3])
        : "r"(a[0]), "r"(a[1]), "r"(a[2]), "r"(a[3]), "r"(b[0]), "r"(b[1]));
}

__global__ __launch_bounds__(256) void hmma_gemm_all_kernel() {
    extern __shared__ __align__(1024) char dsm[];
    uint32_t sbase = smem_u32(dsm);

    int tid = threadIdx.x;
    int wid = tid >> 5;
    int lane = tid & 31;

    int id = blockIdx.x;
    int s = 0;
    #pragma unroll
    for (int q = 1; q < 13; q++) if (id >= cg_tileStart[q]) s = q;
    int local = id - cg_tileStart[s];
    int K = cg_Ksub[s];
    int N = cg_Nsub[s];
    int gx = N >> 7;
    int bcolt = local % gx, browt = local / gx;
    int brow = browt << 7, bcol = bcolt << 7;

    const __half* A = g_U + (size_t)NS * cg_Up[s];
    const __half* B = g_W + cg_Wpref[s];
    __half* C = g_Z + (size_t)NS * cg_Zp[s];

    int r = tid >> 1, q2 = tid & 1;
    const char* gA = (const char*)(A + (size_t)(brow + r) * K + q2 * 32);
    const char* gB = (const char*)(B + (size_t)(bcol + r) * K + q2 * 32);
    uint32_t sts[4];
    #pragma unroll
    for (int i = 0; i < 4; i++) {
        uint32_t off = (uint32_t)r * 128u + (uint32_t)(q2 * 4 + i) * 16u;
        sts[i] = off ^ ((off >> 3) & 0x70);
    }

    int wm = wid >> 1, wn = wid & 1;
    uint32_t a_row[2], a_rx[2];
    #pragma unroll
    for (int mt = 0; mt < 2; mt++) {
        int row = wm * 32 + mt * 16 + (lane & 15);
        a_row[mt] = (uint32_t)row * 128u;
        a_rx[mt] = (uint32_t)(row & 7) << 4;
    }
    uint32_t a_cb = ((lane >> 4) & 1) * 16u;
    int nloc = (lane & 7) + ((lane & 16) >> 1);
    uint32_t b_row[4], b_rx[4];
    #pragma unroll
    for (int nt4 = 0; nt4 < 4; nt4++) {
        int nrow = wn * 64 + nt4 * 16 + nloc;
        b_row[nt4] = (uint32_t)nrow * 128u;
        b_rx[nt4] = (uint32_t)(nrow & 7) << 4;
    }
    uint32_t b_cb = ((lane >> 3) & 1) * 16u;

    float acc[2][8][4];
    #pragma unroll
    for (int mt = 0; mt < 2; mt++)
        #pragma unroll
        for (int nt = 0; nt < 8; nt++)
            #pragma unroll
            for (int e = 0; e < 4; e++) acc[mt][nt][e] = 0.f;

    int NC = K >> 6;

    #pragma unroll
    for (int p = 0; p < 2; p++) {
        uint32_t aS = sbase + (uint32_t)p * 32768u;
        uint32_t bS = aS + 16384u;
        const char* Ap = gA + (size_t)p * 128;
        const char* Bp = gB + (size_t)p * 128;
        #pragma unroll
        for (int i = 0; i < 4; i++) {
            CP_ASYNC16(aS + sts[i], Ap + i * 16);
            CP_ASYNC16(bS + sts[i], Bp + i * 16);
        }
        CP_COMMIT();
    }

    for (int c = 0; c < NC; ++c) {
        if (c + 1 < NC) CP_WAIT1(); else CP_WAIT0();
        __syncthreads();
        if (c + 2 < NC) {
            int st = (c + 2) % 3;
            uint32_t aS = sbase + (uint32_t)st * 32768u;
            uint32_t bS = aS + 16384u;
            const char* Ap = gA + (size_t)(c + 2) * 128;
            const char* Bp = gB + (size_t)(c + 2) * 128;
            #pragma unroll
            for (int i = 0; i < 4; i++) {
                CP_ASYNC16(aS + sts[i], Ap + i * 16);
                CP_ASYNC16(bS + sts[i], Bp + i * 16);
            }
            CP_COMMIT();
        }
        int cst = c % 3;
        uint32_t aS = sbase + (uint32_t)cst * 32768u;
        uint32_t bS = aS + 16384u;
        #pragma unroll
        for (int kq = 0; kq < 4; kq++) {
            uint32_t kb = (uint32_t)kq * 32u;
            uint32_t afr[2][4];
            #pragma unroll
            for (int mt = 0; mt < 2; mt++)
                LDSM_X4(afr[mt][0], afr[mt][1], afr[mt][2], afr[mt][3],
                        aS + a_row[mt] + ((a_cb + kb) ^ a_rx[mt]));
            uint32_t bfr[4][4];
            #pragma unroll
            for (int nt4 = 0; nt4 < 4; nt4++)
                LDSM_X4(bfr[nt4][0], bfr[nt4][1], bfr[nt4][2], bfr[nt4][3],
                        bS + b_row[nt4] + ((b_cb + kb) ^ b_rx[nt4]));
            #pragma unroll
            for (int mt = 0; mt < 2; mt++)
                #pragma unroll
                for (int nt = 0; nt < 8; nt++)
                    hmma16816(acc[mt][nt], afr[mt], &bfr[nt >> 1][(nt & 1) * 2]);
        }
    }

    int g2 = lane >> 2, t2 = lane & 3;
    #pragma unroll
    for (int mt = 0; mt < 2; mt++) {
        #pragma unroll
        for (int nt = 0; nt < 8; nt++) {
            int row0 = brow + wm * 32 + mt * 16 + g2;
            int col = bcol + wn * 64 + nt * 8 + t2 * 2;
            __half2 h0 = __floats2half2_rn(acc[mt][nt][0], acc[mt][nt][1]);
            __half2 h1 = __floats2half2_rn(acc[mt][nt][2], acc[mt][nt][3]);
            *(__half2*)(C + (size_t)row0 * N + col) = h0;
            *(__half2*)(C + (size_t)(row0 + 8) * N + col) = h1;
        }
    }
}

// =======================================================================
// Kernel 5: combine fp16 Karatsuba outputs (+bias), rotate in place, write out
// =======================================================================
__global__ __launch_bounds__(256) void scatter_rot_kernel(const float* __restrict__ fc0_b,
                                                          const float* __restrict__ R,
                                                          float* __restrict__ out) {
    int n = blockIdx.x;
    __shared__ float pre[DIMX];
    __shared__ float dt[164];
    __shared__ float t1s[164];

    compute_DT_smem(n, R, dt, t1s, threadIdx.x);

    for (int j = threadIdx.x * 2; j < 640; j += 512) {
        __half2 hz = *(const __half2*)&g_Z[(size_t)n * 640 + j];
        int l = j >> 7, k = j & 127;
        int base = 128*l*l;
        int d = 2*l + 1;
        pre[base + k*d + l]       = __low2float(hz)  + fc0_b[j];
        pre[base + (k+1)*d + l]   = __high2float(hz) + fc0_b[j+1];
    }
    #define SCAT(MM, CO, P0, P1, P2)                                         \
    for (int tb = threadIdx.x * 2; tb < CO; tb += 512) {                     \
        __half2 h1 = *(const __half2*)&g_Z[(size_t)NS * P0 + (size_t)n * CO + tb]; \
        __half2 h2 = *(const __half2*)&g_Z[(size_t)NS * P1 + (size_t)n * CO + tb]; \
        __half2 h3 = *(const __half2*)&g_Z[(size_t)NS * P2 + (size_t)n * CO + tb]; \
        float v1a = __low2float(h1), v1b = __high2float(h1);                 \
        float v2a = __low2float(h2), v2b = __high2float(h2);                 \
        float v3a = __low2float(h3), v3b = __high2float(h3);                 \
        float rea = v1a - v2a, reb = v1b - v2b;                              \
        float ima = v3a - v1a - v2a, imb = v3b - v1b - v2b;                  \
        int ph = tb >> 1;                                                    \
        int p1 = (CO >> 1) + ph;                                             \
        int l0 = MM + (ph >> 7), k0 = ph & 127;                              \
        int l1 = MM + (p1 >> 7), k1 = p1 & 127;                              \
        int b0 = 128*l0*l0 + k0*(2*l0 + 1);                                  \
        int b1 = 128*l1*l1 + k1*(2*l1 + 1);                                  \
        pre[b0 + l0 - MM] = rea;                                             \
        pre[b0 + l0 + MM] = reb;                                             \
        pre[b1 + l1 - MM] = ima;                                             \
        pre[b1 + l1 + MM] = imb;                                             \
    }
    SCAT(1, 512, 640, 1152, 1664)
    SCAT(2, 384, 2176, 2560, 2944)
    SCAT(3, 256, 3328, 3584, 3840)
    SCAT(4, 128, 4096, 4224, 4352)
    __syncthreads();

    int k = threadIdx.x & 127;
    int h = threadIdx.x >> 7;
    #define ROTO(D, DTO, XO) do {                                            \
        float* pb = pre + XO + k * D;                                        \
        float xv[D];                                                         \
        _Pragma("unroll") for (int j = 0; j < D; j++) xv[j] = pb[j];         \
        _Pragma("unroll") for (int i = 0; i < D; i++) {                      \
            const float* ddp = dt + DTO + i * D;                             \
            float v = 0.f;                                                   \
            _Pragma("unroll") for (int j = 0; j < D; j++) v += ddp[j] * xv[j]; \
            pb[i] = v;                                                       \
        }                                                                    \
    } while (0)
    if (h == 0) { ROTO(3, 0, 128);  ROTO(9, 83, 2048); }
    else        { ROTO(5, 9, 512);  ROTO(7, 34, 1152); }
    __syncthreads();

    float4* orow4 = (float4*)(out + (size_t)n * DIMX);
    for (int c = threadIdx.x; c < DIMX/4; c += 256) orow4[c] = ((const float4*)pre)[c];
}

// =======================================================================
// launch
// =======================================================================
extern "C" void kernel_launch(void* const* d_in, const int* in_sizes, int n_in,
                              void* d_out, int out_size) {
    const float* x     = (const float*)d_in[0];
    const float* R     = (const float*)d_in[1];
    const float* fc0_w = (const float*)d_in[2];
    const float* fc0_b = (const float*)d_in[3];
    const float* w1    = (const float*)d_in[4];
    const float* w2    = (const float*)d_in[5];
    const float* w3    = (const float*)d_in[6];
    const float* w4    = (const float*)d_in[7];
    float* out = (float*)d_out;

    // blocks: 1 (J) + ceil(1802240/384) = 1 + 4694
    build_all_kernel<<<4695, 384>>>(fc0_w, w1, w2, w3, w4);
    rot_gather_kernel<<<NS, 256>>>(x, R);

    cudaFuncSetAttribute(hmma_gemm_all_kernel,
                         cudaFuncAttributeMaxDynamicSharedMemorySize, 98304);
    hmma_gemm_all_kernel<<<4480, 256, 98304>>>();

    scatter_rot_kernel<<<NS, 256>>>(fc0_b, R, out);
}

// round 16
// speedup vs baseline: 1.2469x; 1.0486x over previous
#include <cuda_runtime.h>
#include <cuda_fp16.h>
#include <math.h>
#include <stdint.h>

// ---------------- problem constants ----------------
#define NS    16384
#define DIMX  3200
#define LMAX  4

__constant__ int c_offD[4] = {0, 9, 34, 83};

// 13 sub-GEMMs: 0: m0 (N=640, K=512); per m=1..4: A, B, A+B (co x co)
__constant__ int cg_tileStart[14] = {0,640,1152,1664,2176,2560,2944,3328,3584,3840,4096,4224,4352,4480};
__constant__ int cg_Ksub[13]  = {512,512,512,512,384,384,384,256,256,256,128,128,128};
__constant__ int cg_Nsub[13]  = {640,512,512,512,384,384,384,256,256,256,128,128,128};
__constant__ int cg_Up[13]    = {0,512,1024,1536,2048,2432,2816,3200,3456,3712,3968,4096,4224};
__constant__ int cg_Zp[13]    = {0,640,1152,1664,2176,2560,2944,3328,3584,3840,4096,4224,4352};
__constant__ int cg_Wpref[14] = {0,327680,589824,851968,1114112,1261568,1409024,1556480,1622016,1687552,1753088,1769472,1785856,1802240};

// ---------------- device scratch ----------------
__device__ float g_J[164];
__device__ float g_DT[(size_t)NS * 164];      // per-sample D^T (written by rot_gather)
__device__ __half g_W[1802240];
__device__ __half g_U[(size_t)NS * 4352];
__device__ __half g_Z[(size_t)NS * 4480];     // fp16 GEMM outputs

// =======================================================================
// Kernel 0+1 merged: block 0 builds J (fp64); blocks >=1 build W (fp16)
// =======================================================================
__device__ void build_J_block() {
    __shared__ double Xr[4][81], Xi[4][81], Qr[4][81], Qi[4][81];
    __shared__ double Sa[4][81], Se[4][81], St[4][81];
    int g = threadIdx.x / 96;
    int e = threadIdx.x % 96;
    int l = g + 1, d = 2*l + 1, dd = d*d;
    const double j = (double)l;
    const double SQ12 = 0.70710678118654752440;
    const double PI_D = 3.14159265358979323846;

    if (e < 81) { Xr[g][e]=0; Xi[g][e]=0; Qr[g][e]=0; Qi[g][e]=0; }
    __syncthreads();
    if (e == 0) {
        for (int i2 = 0; i2 < d-1; i2++) {
            double m  = -j + (double)i2;
            double rv = -sqrt(j*(j+1.0) - m*(m+1.0));
            Xr[g][(i2+1)*d + i2] += 0.5 * rv;
            double m2 = -j + 1.0 + (double)i2;
            double lv = sqrt(j*(j+1.0) - m2*(m2-1.0));
            Xr[g][i2*d + (i2+1)] += 0.5 * lv;
        }
        for (int i2 = 0; i2 < d; i2++) Xi[g][i2*d + i2] += (-j + (double)i2);
        for (int m = 1; m <= l; m++) {
            int r = l - m;
            Qr[g][r*d + (l+m)] = SQ12;
            Qi[g][r*d + r]     = -SQ12;
            int r2 = l + m;
            double sgn = (m & 1) ? -1.0 : 1.0;
            Qr[g][r2*d + r2]     = sgn * SQ12;
            Qi[g][r2*d + (l-m)]  = sgn * SQ12;
        }
        Qr[g][l*d + l] = 1.0;
    }
    __syncthreads();
    if (e < dd) {
        int i = e / d, jj = e % d;
        double s = 0.0;
        for (int k = 0; k < d; k++) {
            double mr = 0.0, mi = 0.0;
            for (int p = 0; p < d; p++) {
                mr += Xr[g][k*d+p]*Qr[g][p*d+jj] - Xi[g][k*d+p]*Qi[g][p*d+jj];
                mi += Xr[g][k*d+p]*Qi[g][p*d+jj] + Xi[g][k*d+p]*Qr[g][p*d+jj];
            }
            s += Qr[g][k*d+i]*mr + Qi[g][k*d+i]*mi;
        }
        Sa[g][e] = (PI_D * SQ12) * s * (1.0/1024.0);
        Se[g][e] = (i == jj) ? 1.0 : 0.0;
        St[g][e] = (i == jj) ? 1.0 : 0.0;
    }
    __syncthreads();
    for (int k = 1; k < 24; k++) {
        double v = 0.0;
        if (e < dd) {
            int i = e / d, jj = e % d;
            double s = 0.0;
            for (int p = 0; p < d; p++) s += St[g][i*d+p] * Sa[g][p*d+jj];
            v = s / (double)k;
        }
        __syncthreads();
        if (e < dd) { St[g][e] = v; Se[g][e] += v; }
        __syncthreads();
    }
    for (int s2 = 0; s2 < 10; s2++) {
        double v = 0.0;
        if (e < dd) {
            int i = e / d, jj = e % d;
            double s = 0.0;
            for (int p = 0; p < d; p++) s += Se[g][i*d+p] * Se[g][p*d+jj];
            v = s;
        }
        __syncthreads();
        if (e < dd) Se[g][e] = v;
        __syncthreads();
    }
    if (e < dd) g_J[c_offD[g] + e] = (float)Se[g][e];
}

__global__ __launch_bounds__(384) void build_all_kernel(
        const float* __restrict__ fc0_w,
        const float* __restrict__ w1, const float* __restrict__ w2,
        const float* __restrict__ w3, const float* __restrict__ w4) {
    if (blockIdx.x == 0) {
        build_J_block();
        return;
    }
    int gid = (blockIdx.x - 1) * 384 + threadIdx.x;
    if (gid >= 1802240) return;
    int s = 0;
    #pragma unroll
    for (int q = 1; q < 13; q++) if (gid >= cg_Wpref[q]) s = q;
    int local = gid - cg_Wpref[s];
    int K = cg_Ksub[s];
    int o = local / K;
    int t = local - o * K;
    float v;
    if (s == 0) {
        v = fc0_w[o * 640 + t + 128];
    } else {
        int m = (s - 1) / 3 + 1;
        int which = (s - 1) % 3;
        const float* w = (m == 1) ? w1 : (m == 2) ? w2 : (m == 3) ? w3 : w4;
        if (which == 0)      v = w[o * K + t];
        else if (which == 1) v = w[(K + o) * K + t];
        else                 v = w[o * K + t] + w[(K + o) * K + t];
    }
    g_W[gid] = __float2half_rn(v);
}

// =======================================================================
// In-CTA Wigner D^T (optimized trig): warps 0-3 compute l = wid+1 into dt[].
// Per-row trig computed once by lanes 0..d-1 (identical expressions ->
// bit-exact vs per-element version).
// =======================================================================
__device__ __forceinline__ void compute_DT_smem(int n, const float* __restrict__ R,
                                                float* dt, float* t1, int tid) {
    __shared__ float s_cb[4][9], s_sb[4][9], s_ca[4][9], s_sa[4][9];
    int wid = tid >> 5, lane = tid & 31;
    if (wid >= 4) return;
    int l = wid + 1, d = 2*l + 1, dd = d*d;

    float vx = R[n*3 + 1], vy = R[n*3 + 2], vz = R[n*3 + 0];
    float nrm = sqrtf(vx*vx + vy*vy + vz*vz);
    nrm = fmaxf(nrm, 1e-12f);
    vx /= nrm; vy /= nrm; vz /= nrm;
    vx = fminf(fmaxf(vx, -1.f), 1.f);
    vy = fminf(fmaxf(vy, -1.f), 1.f);
    vz = fminf(fmaxf(vz, -1.f), 1.f);
    float beta  = acosf(vy);
    float alpha = atan2f(vx, vz);

    if (lane < d) {
        float fr = (float)(l - lane);
        s_cb[wid][lane] = cosf(fr * beta);
        s_sb[wid][lane] = sinf(fr * beta);
        s_ca[wid][lane] = cosf(fr * alpha);
        s_sa[wid][lane] = sinf(fr * alpha);
    }
    __syncwarp();

    const float* J = g_J + c_offD[l-1];
    float* T1 = t1 + c_offD[l-1];
    float* DD = dt + c_offD[l-1];

    // T1 = Z(beta) @ J
    for (int e = lane; e < dd; e += 32) {
        int i = e / d, jj = e - i * d;
        T1[e] = s_cb[wid][i] * J[e] + s_sb[wid][i] * J[(d - 1 - i)*d + jj];
    }
    __syncwarp();
    // T2 = J @ T1 (into DD)
    for (int e = lane; e < dd; e += 32) {
        int i = e / d, jj = e - i * d;
        float s2 = 0.f;
        for (int k = 0; k < d; k++) s2 += J[i*d + k] * T1[k*d + jj];
        DD[e] = s2;
    }
    __syncwarp();
    // D = Z(alpha) @ T2 (regs), then D^T
    float dv[3]; int cnt = 0;
    for (int e = lane; e < dd; e += 32) {
        int i = e / d, jj = e - i * d;
        dv[cnt++] = s_ca[wid][i] * DD[i*d + jj] + s_sa[wid][i] * DD[(d - 1 - i)*d + jj];
    }
    __syncwarp();
    cnt = 0;
    for (int e = lane; e < dd; e += 32) {
        int i = e / d, jj = e - i * d;
        DD[jj*d + i] = dv[cnt++];
    }
}

// =======================================================================
// Kernel 3: rotate x in-place (block-per-thread), gather fp16 inputs (half2),
//           store dt to global for scatter reuse
// =======================================================================
__global__ __launch_bounds__(256) void rot_gather_kernel(const float* __restrict__ x,
                                                         const float* __restrict__ R) {
    int n = blockIdx.x;
    __shared__ float xs[DIMX];
    __shared__ float dt[164];
    __shared__ float t1s[164];
    const float4* xr4 = (const float4*)(x + (size_t)n * DIMX);
    for (int c = threadIdx.x; c < DIMX/4; c += 256) ((float4*)xs)[c] = xr4[c];
    compute_DT_smem(n, R, dt, t1s, threadIdx.x);
    __syncthreads();

    // persist dt for scatter kernel
    for (int c = threadIdx.x; c < 164; c += 256) g_DT[(size_t)n * 164 + c] = dt[c];

    int k = threadIdx.x & 127;
    int h = threadIdx.x >> 7;
    #define ROTBLK(D, DTO, XO) do {                                          \
        float* xb = xs + XO + k * D;                                         \
        float xv[D];                                                         \
        _Pragma("unroll") for (int j = 0; j < D; j++) xv[j] = xb[j];         \
        _Pragma("unroll") for (int i = 0; i < D; i++) {                      \
            const float* ddp = dt + DTO + i * D;                             \
            float v = 0.f;                                                   \
            _Pragma("unroll") for (int j = 0; j < D; j++) v += ddp[j] * xv[j]; \
            xb[i] = v;                                                       \
        }                                                                    \
    } while (0)
    if (h == 0) { ROTBLK(3, 0, 128);  ROTBLK(9, 83, 2048); }
    else        { ROTBLK(5, 9, 512);  ROTBLK(7, 34, 1152); }
    __syncthreads();

    {
        int j = threadIdx.x * 2;
        if (j < 512) {
            int jj = j + 128;
            int l = jj >> 7, kk = jj & 127;
            int d = 2*l + 1;
            float va = xs[128*l*l + kk*d + l];
            float vb = xs[128*l*l + (kk+1)*d + l];
            *(__half2*)&g_U[(size_t)n * 512 + j] = __floats2half2_rn(va, vb);
        }
    }
    #define GATH(MM, CO, P0, P1, P2)                                         \
    for (int tb = threadIdx.x * 2; tb < CO; tb += 512) {                     \
        int ph = tb >> 1;                                                    \
        int l0 = MM + (ph >> 7), k0 = ph & 127;                              \
        int p1 = (CO >> 1) + ph;                                             \
        int l1 = MM + (p1 >> 7), k1 = p1 & 127;                              \
        int b0 = 128*l0*l0 + k0*(2*l0 + 1);                                  \
        int b1 = 128*l1*l1 + k1*(2*l1 + 1);                                  \
        float u0a = xs[b0 + l0 - MM], u0b = xs[b0 + l0 + MM];                \
        float u1a = xs[b1 + l1 - MM], u1b = xs[b1 + l1 + MM];                \
        *(__half2*)&g_U[(size_t)NS * P0 + (size_t)n * CO + tb] = __floats2half2_rn(u0a, u0b); \
        *(__half2*)&g_U[(size_t)NS * P1 + (size_t)n * CO + tb] = __floats2half2_rn(u1a, u1b); \
        *(__half2*)&g_U[(size_t)NS * P2 + (size_t)n * CO + tb] = __floats2half2_rn(u0a + u1a, u0b + u1b); \
    }
    GATH(1, 512, 512, 1024, 1536)
    GATH(2, 384, 2048, 2432, 2816)
    GATH(3, 256, 3200, 3456, 3712)
    GATH(4, 128, 3968, 4096, 4224)
}

// =======================================================================
// Kernel 4: HMMA fp16 GEMM over 13 sub-GEMMs
//   128x128 CTA tile, 256 threads (8 warps of 32x64), 3-stage cp.async
// =======================================================================
__device__ __forceinline__ uint32_t smem_u32(const void* p) {
    uint32_t a;
    asm("{ .reg .u64 t; cvta.to.shared.u64 t, %1; cvt.u32.u64 %0, t; }" : "=r"(a) : "l"(p));
    return a;
}
#define CP_ASYNC16(dst, src) \
    asm volatile("cp.async.cg.shared.global [%0], [%1], 16;" :: "r"(dst), "l"(src) : "memory")
#define CP_COMMIT() asm volatile("cp.async.commit_group;" ::: "memory")
#define CP_WAIT1()  asm volatile("cp.async.wait_group 1;" ::: "memory")
#define CP_WAIT0()  asm volatile("cp.async.wait_group 0;" ::: "memory")
#define LDSM_X4(r0, r1, r2, r3, addr) \
    asm volatile("ldmatrix.sync.aligned.m8n8.x4.shared.b16 {%0,%1,%2,%3}, [%4];" \
                 : "=r"(r0), "=r"(r1), "=r"(r2), "=r"(r3) : "r"(addr))

__device__ __forceinline__ void hmma16816(float* c, const uint32_t* a, const uint32_t* b) {
    asm volatile(
        "mma.sync.aligned.m16n8k16.row.col.f32.f16.f16.f32 "
        "{%0,%1,%2,%3}, {%4,%5,%6,%7}, {%8,%9}, {%0,%1,%2,%3};"
        : "+f"(c[0]), "+f"(c[1]), "+f"(c[2]), "+f"(c[3])
        : "r"(a[0]), "r"(a[1]), "r"(a[2]), "r"(a[3]), "r"(b[0]), "r"(b[1]));
}

__global__ __launch_bounds__(256) void hmma_gemm_all_kernel() {
    extern __shared__ __align__(1024) char dsm[];
    uint32_t sbase = smem_u32(dsm);

    int tid = threadIdx.x;
    int wid = tid >> 5;
    int lane = tid & 31;

    int id = blockIdx.x;
    int s = 0;
    #pragma unroll
    for (int q = 1; q < 13; q++) if (id >= cg_tileStart[q]) s = q;
    int local = id - cg_tileStart[s];
    int K = cg_Ksub[s];
    int N = cg_Nsub[s];
    int gx = N >> 7;
    int bcolt = local % gx, browt = local / gx;
    int brow = browt << 7, bcol = bcolt << 7;

    const __half* A = g_U + (size_t)NS * cg_Up[s];
    const __half* B = g_W + cg_Wpref[s];
    __half* C = g_Z + (size_t)NS * cg_Zp[s];

    int r = tid >> 1, q2 = tid & 1;
    const char* gA = (const char*)(A + (size_t)(brow + r) * K + q2 * 32);
    const char* gB = (const char*)(B + (size_t)(bcol + r) * K + q2 * 32);
    uint32_t sts[4];
    #pragma unroll
    for (int i = 0; i < 4; i++) {
        uint32_t off = (uint32_t)r * 128u + (uint32_t)(q2 * 4 + i) * 16u;
        sts[i] = off ^ ((off >> 3) & 0x70);
    }

    int wm = wid >> 1, wn = wid & 1;
    uint32_t a_row[2], a_rx[2];
    #pragma unroll
    for (int mt = 0; mt < 2; mt++) {
        int row = wm * 32 + mt * 16 + (lane & 15);
        a_row[mt] = (uint32_t)row * 128u;
        a_rx[mt] = (uint32_t)(row & 7) << 4;
    }
    uint32_t a_cb = ((lane >> 4) & 1) * 16u;
    int nloc = (lane & 7) + ((lane & 16) >> 1);
    uint32_t b_row[4], b_rx[4];
    #pragma unroll
    for (int nt4 = 0; nt4 < 4; nt4++) {
        int nrow = wn * 64 + nt4 * 16 + nloc;
        b_row[nt4] = (uint32_t)nrow * 128u;
        b_rx[nt4] = (uint32_t)(nrow & 7) << 4;
    }
    uint32_t b_cb = ((lane >> 3) & 1) * 16u;

    float acc[2][8][4];
    #pragma unroll
    for (int mt = 0; mt < 2; mt++)
        #pragma unroll
        for (int nt = 0; nt < 8; nt++)
            #pragma unroll
            for (int e = 0; e < 4; e++) acc[mt][nt][e] = 0.f;

    int NC = K >> 6;

    #pragma unroll
    for (int p = 0; p < 2; p++) {
        uint32_t aS = sbase + (uint32_t)p * 32768u;
        uint32_t bS = aS + 16384u;
        const char* Ap = gA + (size_t)p * 128;
        const char* Bp = gB + (size_t)p * 128;
        #pragma unroll
        for (int i = 0; i < 4; i++) {
            CP_ASYNC16(aS + sts[i], Ap + i * 16);
            CP_ASYNC16(bS + sts[i], Bp + i * 16);
        }
        CP_COMMIT();
    }

    for (int c = 0; c < NC; ++c) {
        if (c + 1 < NC) CP_WAIT1(); else CP_WAIT0();
        __syncthreads();
        if (c + 2 < NC) {
            int st = (c + 2) % 3;
            uint32_t aS = sbase + (uint32_t)st * 32768u;
            uint32_t bS = aS + 16384u;
            const char* Ap = gA + (size_t)(c + 2) * 128;
            const char* Bp = gB + (size_t)(c + 2) * 128;
            #pragma unroll
            for (int i = 0; i < 4; i++) {
                CP_ASYNC16(aS + sts[i], Ap + i * 16);
                CP_ASYNC16(bS + sts[i], Bp + i * 16);
            }
            CP_COMMIT();
        }
        int cst = c % 3;
        uint32_t aS = sbase + (uint32_t)cst * 32768u;
        uint32_t bS = aS + 16384u;
        #pragma unroll
        for (int kq = 0; kq < 4; kq++) {
            uint32_t kb = (uint32_t)kq * 32u;
            uint32_t afr[2][4];
            #pragma unroll
            for (int mt = 0; mt < 2; mt++)
                LDSM_X4(afr[mt][0], afr[mt][1], afr[mt][2], afr[mt][3],
                        aS + a_row[mt] + ((a_cb + kb) ^ a_rx[mt]));
            uint32_t bfr[4][4];
            #pragma unroll
            for (int nt4 = 0; nt4 < 4; nt4++)
                LDSM_X4(bfr[nt4][0], bfr[nt4][1], bfr[nt4][2], bfr[nt4][3],
                        bS + b_row[nt4] + ((b_cb + kb) ^ b_rx[nt4]));
            #pragma unroll
            for (int mt = 0; mt < 2; mt++)
                #pragma unroll
                for (int nt = 0; nt < 8; nt++)
                    hmma16816(acc[mt][nt], afr[mt], &bfr[nt >> 1][(nt & 1) * 2]);
        }
    }

    int g2 = lane >> 2, t2 = lane & 3;
    #pragma unroll
    for (int mt = 0; mt < 2; mt++) {
        #pragma unroll
        for (int nt = 0; nt < 8; nt++) {
            int row0 = brow + wm * 32 + mt * 16 + g2;
            int col = bcol + wn * 64 + nt * 8 + t2 * 2;
            __half2 h0 = __floats2half2_rn(acc[mt][nt][0], acc[mt][nt][1]);
            __half2 h1 = __floats2half2_rn(acc[mt][nt][2], acc[mt][nt][3]);
            *(__half2*)(C + (size_t)row0 * N + col) = h0;
            *(__half2*)(C + (size_t)(row0 + 8) * N + col) = h1;
        }
    }
}

// =======================================================================
// Kernel 5: combine fp16 Karatsuba outputs (+bias), rotate in place, write out
//           (dt loaded from global, computed by rot_gather)
// =======================================================================
__global__ __launch_bounds__(256) void scatter_rot_kernel(const float* __restrict__ fc0_b,
                                                          float* __restrict__ out) {
    int n = blockIdx.x;
    __shared__ float pre[DIMX];
    __shared__ float dt[164];

    for (int c = threadIdx.x; c < 164; c += 256) dt[c] = g_DT[(size_t)n * 164 + c];

    for (int j = threadIdx.x * 2; j < 640; j += 512) {
        __half2 hz = *(const __half2*)&g_Z[(size_t)n * 640 + j];
        int l = j >> 7, k = j & 127;
        int base = 128*l*l;
        int d = 2*l + 1;
        pre[base + k*d + l]       = __low2float(hz)  + fc0_b[j];
        pre[base + (k+1)*d + l]   = __high2float(hz) + fc0_b[j+1];
    }
    #define SCAT(MM, CO, P0, P1, P2)                                         \
    for (int tb = threadIdx.x * 2; tb < CO; tb += 512) {                     \
        __half2 h1 = *(const __half2*)&g_Z[(size_t)NS * P0 + (size_t)n * CO + tb]; \
        __half2 h2 = *(const __half2*)&g_Z[(size_t)NS * P1 + (size_t)n * CO + tb]; \
        __half2 h3 = *(const __half2*)&g_Z[(size_t)NS * P2 + (size_t)n * CO + tb]; \
        float v1a = __low2float(h1), v1b = __high2float(h1);                 \
        float v2a = __low2float(h2), v2b = __high2float(h2);                 \
        float v3a = __low2float(h3), v3b = __high2float(h3);                 \
        float rea = v1a - v2a, reb = v1b - v2b;                              \
        float ima = v3a - v1a - v2a, imb = v3b - v1b - v2b;                  \
        int ph = tb >> 1;                                                    \
        int p1 = (CO >> 1) + ph;                                             \
        int l0 = MM + (ph >> 7), k0 = ph & 127;                              \
        int l1 = MM + (p1 >> 7), k1 = p1 & 127;                              \
        int b0 = 128*l0*l0 + k0*(2*l0 + 1);                                  \
        int b1 = 128*l1*l1 + k1*(2*l1 + 1);                                  \
        pre[b0 + l0 - MM] = rea;                                             \
        pre[b0 + l0 + MM] = reb;                                             \
        pre[b1 + l1 - MM] = ima;                                             \
        pre[b1 + l1 + MM] = imb;                                             \
    }
    SCAT(1, 512, 640, 1152, 1664)
    SCAT(2, 384, 2176, 2560, 2944)
    SCAT(3, 256, 3328, 3584, 3840)
    SCAT(4, 128, 4096, 4224, 4352)
    __syncthreads();

    int k = threadIdx.x & 127;
    int h = threadIdx.x >> 7;
    #define ROTO(D, DTO, XO) do {                                            \
        float* pb = pre + XO + k * D;                                        \
        float xv[D];                                                         \
        _Pragma("unroll") for (int j = 0; j < D; j++) xv[j] = pb[j];         \
        _Pragma("unroll") for (int i = 0; i < D; i++) {                      \
            const float* ddp = dt + DTO + i * D;                             \
            float v = 0.f;                                                   \
            _Pragma("unroll") for (int j = 0; j < D; j++) v += ddp[j] * xv[j]; \
            pb[i] = v;                                                       \
        }                                                                    \
    } while (0)
    if (h == 0) { ROTO(3, 0, 128);  ROTO(9, 83, 2048); }
    else        { ROTO(5, 9, 512);  ROTO(7, 34, 1152); }
    __syncthreads();

    float4* orow4 = (float4*)(out + (size_t)n * DIMX);
    for (int c = threadIdx.x; c < DIMX/4; c += 256) orow4[c] = ((const float4*)pre)[c];
}

// =======================================================================
// launch
// =======================================================================
extern "C" void kernel_launch(void* const* d_in, const int* in_sizes, int n_in,
                              void* d_out, int out_size) {
    const float* x     = (const float*)d_in[0];
    const float* R     = (const float*)d_in[1];
    const float* fc0_w = (const float*)d_in[2];
    const float* fc0_b = (const float*)d_in[3];
    const float* w1    = (const float*)d_in[4];
    const float* w2    = (const float*)d_in[5];
    const float* w3    = (const float*)d_in[6];
    const float* w4    = (const float*)d_in[7];
    float* out = (float*)d_out;

    build_all_kernel<<<4695, 384>>>(fc0_w, w1, w2, w3, w4);
    rot_gather_kernel<<<NS, 256>>>(x, R);

    cudaFuncSetAttribute(hmma_gemm_all_kernel,
                         cudaFuncAttributeMaxDynamicSharedMemorySize, 98304);
    hmma_gemm_all_kernel<<<4480, 256, 98304>>>();

    scatter_rot_kernel<<<NS, 256>>>(fc0_b, out);
}

// round 17
// speedup vs baseline: 1.2531x; 1.0050x over previous
#include <cuda_runtime.h>
#include <cuda_fp16.h>
#include <math.h>
#include <stdint.h>

// ---------------- problem constants ----------------
#define NS    16384
#define DIMX  3200
#define LMAX  4

__constant__ int c_offD[4] = {0, 9, 34, 83};

// 13 sub-GEMMs: 0: m0 (N=640, K=512); per m=1..4: A, B, A+B (co x co)
__constant__ int cg_tileStart[14] = {0,640,1152,1664,2176,2560,2944,3328,3584,3840,4096,4224,4352,4480};
__constant__ int cg_Ksub[13]  = {512,512,512,512,384,384,384,256,256,256,128,128,128};
__constant__ int cg_Nsub[13]  = {640,512,512,512,384,384,384,256,256,256,128,128,128};
__constant__ int cg_Up[13]    = {0,512,1024,1536,2048,2432,2816,3200,3456,3712,3968,4096,4224};
__constant__ int cg_Zp[13]    = {0,640,1152,1664,2176,2560,2944,3328,3584,3840,4096,4224,4352};
__constant__ int cg_Wpref[14] = {0,327680,589824,851968,1114112,1261568,1409024,1556480,1622016,1687552,1753088,1769472,1785856,1802240};

// ---------------- device scratch ----------------
__device__ float g_J[164];
__device__ float g_DT[(size_t)NS * 164];
__device__ __half g_W[1802240];
__device__ __half g_U[(size_t)NS * 4352];
__device__ __half g_Z[(size_t)NS * 4480];

// =======================================================================
// Kernel 0: build J matrices (fp64, one CTA)
// =======================================================================
__global__ __launch_bounds__(384) void build_J_kernel() {
    __shared__ double Xr[4][81], Xi[4][81], Qr[4][81], Qi[4][81];
    __shared__ double Sa[4][81], Se[4][81], St[4][81];
    int g = threadIdx.x / 96;
    int e = threadIdx.x % 96;
    int l = g + 1, d = 2*l + 1, dd = d*d;
    const double j = (double)l;
    const double SQ12 = 0.70710678118654752440;
    const double PI_D = 3.14159265358979323846;

    if (e < 81) { Xr[g][e]=0; Xi[g][e]=0; Qr[g][e]=0; Qi[g][e]=0; }
    __syncthreads();
    if (e == 0) {
        for (int i2 = 0; i2 < d-1; i2++) {
            double m  = -j + (double)i2;
            double rv = -sqrt(j*(j+1.0) - m*(m+1.0));
            Xr[g][(i2+1)*d + i2] += 0.5 * rv;
            double m2 = -j + 1.0 + (double)i2;
            double lv = sqrt(j*(j+1.0) - m2*(m2-1.0));
            Xr[g][i2*d + (i2+1)] += 0.5 * lv;
        }
        for (int i2 = 0; i2 < d; i2++) Xi[g][i2*d + i2] += (-j + (double)i2);
        for (int m = 1; m <= l; m++) {
            int r = l - m;
            Qr[g][r*d + (l+m)] = SQ12;
            Qi[g][r*d + r]     = -SQ12;
            int r2 = l + m;
            double sgn = (m & 1) ? -1.0 : 1.0;
            Qr[g][r2*d + r2]     = sgn * SQ12;
            Qi[g][r2*d + (l-m)]  = sgn * SQ12;
        }
        Qr[g][l*d + l] = 1.0;
    }
    __syncthreads();
    if (e < dd) {
        int i = e / d, jj = e % d;
        double s = 0.0;
        for (int k = 0; k < d; k++) {
            double mr = 0.0, mi = 0.0;
            for (int p = 0; p < d; p++) {
                mr += Xr[g][k*d+p]*Qr[g][p*d+jj] - Xi[g][k*d+p]*Qi[g][p*d+jj];
                mi += Xr[g][k*d+p]*Qi[g][p*d+jj] + Xi[g][k*d+p]*Qr[g][p*d+jj];
            }
            s += Qr[g][k*d+i]*mr + Qi[g][k*d+i]*mi;
        }
        Sa[g][e] = (PI_D * SQ12) * s * (1.0/1024.0);
        Se[g][e] = (i == jj) ? 1.0 : 0.0;
        St[g][e] = (i == jj) ? 1.0 : 0.0;
    }
    __syncthreads();
    for (int k = 1; k < 24; k++) {
        double v = 0.0;
        if (e < dd) {
            int i = e / d, jj = e % d;
            double s = 0.0;
            for (int p = 0; p < d; p++) s += St[g][i*d+p] * Sa[g][p*d+jj];
            v = s / (double)k;
        }
        __syncthreads();
        if (e < dd) { St[g][e] = v; Se[g][e] += v; }
        __syncthreads();
    }
    for (int s2 = 0; s2 < 10; s2++) {
        double v = 0.0;
        if (e < dd) {
            int i = e / d, jj = e % d;
            double s = 0.0;
            for (int p = 0; p < d; p++) s += Se[g][i*d+p] * Se[g][p*d+jj];
            v = s;
        }
        __syncthreads();
        if (e < dd) Se[g][e] = v;
        __syncthreads();
    }
    if (e < dd) g_J[c_offD[g] + e] = (float)Se[g][e];
}

// =======================================================================
// In-CTA Wigner D^T (row-trig, bit-exact): warps 0-3, l = wid+1
// =======================================================================
__device__ __forceinline__ void compute_DT_smem(int n, const float* __restrict__ R,
                                                float* dt, float* t1, int tid) {
    __shared__ float s_cb[4][9], s_sb[4][9], s_ca[4][9], s_sa[4][9];
    int wid = tid >> 5, lane = tid & 31;
    if (wid >= 4) return;
    int l = wid + 1, d = 2*l + 1, dd = d*d;

    float vx = R[n*3 + 1], vy = R[n*3 + 2], vz = R[n*3 + 0];
    float nrm = sqrtf(vx*vx + vy*vy + vz*vz);
    nrm = fmaxf(nrm, 1e-12f);
    vx /= nrm; vy /= nrm; vz /= nrm;
    vx = fminf(fmaxf(vx, -1.f), 1.f);
    vy = fminf(fmaxf(vy, -1.f), 1.f);
    vz = fminf(fmaxf(vz, -1.f), 1.f);
    float beta  = acosf(vy);
    float alpha = atan2f(vx, vz);

    if (lane < d) {
        float fr = (float)(l - lane);
        s_cb[wid][lane] = cosf(fr * beta);
        s_sb[wid][lane] = sinf(fr * beta);
        s_ca[wid][lane] = cosf(fr * alpha);
        s_sa[wid][lane] = sinf(fr * alpha);
    }
    __syncwarp();

    const float* J = g_J + c_offD[l-1];
    float* T1 = t1 + c_offD[l-1];
    float* DD = dt + c_offD[l-1];

    for (int e = lane; e < dd; e += 32) {
        int i = e / d, jj = e - i * d;
        T1[e] = s_cb[wid][i] * J[e] + s_sb[wid][i] * J[(d - 1 - i)*d + jj];
    }
    __syncwarp();
    for (int e = lane; e < dd; e += 32) {
        int i = e / d, jj = e - i * d;
        float s2 = 0.f;
        for (int k = 0; k < d; k++) s2 += J[i*d + k] * T1[k*d + jj];
        DD[e] = s2;
    }
    __syncwarp();
    float dv[3]; int cnt = 0;
    for (int e = lane; e < dd; e += 32) {
        int i = e / d, jj = e - i * d;
        dv[cnt++] = s_ca[wid][i] * DD[i*d + jj] + s_sa[wid][i] * DD[(d - 1 - i)*d + jj];
    }
    __syncwarp();
    cnt = 0;
    for (int e = lane; e < dd; e += 32) {
        int i = e / d, jj = e - i * d;
        DD[jj*d + i] = dv[cnt++];
    }
}

// =======================================================================
// Kernel 3 (merged): blocks [0,NS): rotate x + gather; blocks >= NS: build W
// =======================================================================
#define WBLK 3520   // 1802240 / 512 elements (2 per thread)

__global__ __launch_bounds__(256) void rot_gather_buildw_kernel(
        const float* __restrict__ x, const float* __restrict__ R,
        const float* __restrict__ fc0_w,
        const float* __restrict__ w1, const float* __restrict__ w2,
        const float* __restrict__ w3, const float* __restrict__ w4) {
    if (blockIdx.x >= NS) {
        // ---- W build: 2 consecutive elements per thread, half2 store ----
        int gid = ((blockIdx.x - NS) * 256 + threadIdx.x) * 2;
        if (gid >= 1802240) return;
        int s = 0;
        #pragma unroll
        for (int q = 1; q < 13; q++) if (gid >= cg_Wpref[q]) s = q;
        int local = gid - cg_Wpref[s];
        int K = cg_Ksub[s];
        int o = local / K;
        int t = local - o * K;   // even; t+1 in same row (K even)
        float v0, v1v;
        if (s == 0) {
            v0 = fc0_w[o * 640 + t + 128];
            v1v = fc0_w[o * 640 + t + 129];
        } else {
            int m = (s - 1) / 3 + 1;
            int which = (s - 1) % 3;
            const float* w = (m == 1) ? w1 : (m == 2) ? w2 : (m == 3) ? w3 : w4;
            if (which == 0)      { v0 = w[o * K + t];       v1v = w[o * K + t + 1]; }
            else if (which == 1) { v0 = w[(K + o) * K + t]; v1v = w[(K + o) * K + t + 1]; }
            else { v0 = w[o * K + t] + w[(K + o) * K + t];
                   v1v = w[o * K + t + 1] + w[(K + o) * K + t + 1]; }
        }
        *(__half2*)&g_W[gid] = __floats2half2_rn(v0, v1v);
        return;
    }

    int n = blockIdx.x;
    __shared__ float xs[DIMX];
    __shared__ float dt[164];
    __shared__ float t1s[164];
    const float4* xr4 = (const float4*)(x + (size_t)n * DIMX);
    for (int c = threadIdx.x; c < DIMX/4; c += 256) ((float4*)xs)[c] = xr4[c];
    compute_DT_smem(n, R, dt, t1s, threadIdx.x);
    __syncthreads();

    for (int c = threadIdx.x; c < 164; c += 256) g_DT[(size_t)n * 164 + c] = dt[c];

    int k = threadIdx.x & 127;
    int h = threadIdx.x >> 7;
    #define ROTBLK(D, DTO, XO) do {                                          \
        float* xb = xs + XO + k * D;                                         \
        float xv[D];                                                         \
        _Pragma("unroll") for (int j = 0; j < D; j++) xv[j] = xb[j];         \
        _Pragma("unroll") for (int i = 0; i < D; i++) {                      \
            const float* ddp = dt + DTO + i * D;                             \
            float v = 0.f;                                                   \
            _Pragma("unroll") for (int j = 0; j < D; j++) v += ddp[j] * xv[j]; \
            xb[i] = v;                                                       \
        }                                                                    \
    } while (0)
    if (h == 0) { ROTBLK(3, 0, 128);  ROTBLK(9, 83, 2048); }
    else        { ROTBLK(5, 9, 512);  ROTBLK(7, 34, 1152); }
    __syncthreads();

    // m0 segment: 4 diag entries per thread, uint2 store
    {
        int j = threadIdx.x * 4;
        if (j < 512) {
            int jj = j + 128;
            int l = jj >> 7, kk = jj & 127;   // kk..kk+3 same l (j%4==0)
            int d = 2*l + 1;
            int base = 128*l*l;
            __half2 lo = __floats2half2_rn(xs[base + kk*d + l],     xs[base + (kk+1)*d + l]);
            __half2 hi = __floats2half2_rn(xs[base + (kk+2)*d + l], xs[base + (kk+3)*d + l]);
            uint2 pk; pk.x = *(uint32_t*)&lo; pk.y = *(uint32_t*)&hi;
            *(uint2*)&g_U[(size_t)n * 512 + j] = pk;
        }
    }
    // m>=1: 4 flat positions (2 (l,k) pairs) per iteration, uint2 stores
    #define GATH(MM, CO, P0, P1, P2)                                             \
    for (int tb = threadIdx.x * 4; tb < CO; tb += 1024) {                        \
        int phA = tb >> 1, phB = phA + 1;                                        \
        int lA0 = MM + (phA >> 7), kA0 = phA & 127;                              \
        int lB0 = MM + (phB >> 7), kB0 = phB & 127;                              \
        int pA1 = (CO >> 1) + phA, pB1 = (CO >> 1) + phB;                        \
        int lA1 = MM + (pA1 >> 7), kA1 = pA1 & 127;                              \
        int lB1 = MM + (pB1 >> 7), kB1 = pB1 & 127;                              \
        int bA0 = 128*lA0*lA0 + kA0*(2*lA0 + 1);                                 \
        int bB0 = 128*lB0*lB0 + kB0*(2*lB0 + 1);                                 \
        int bA1 = 128*lA1*lA1 + kA1*(2*lA1 + 1);                                 \
        int bB1 = 128*lB1*lB1 + kB1*(2*lB1 + 1);                                 \
        float u0a = xs[bA0 + lA0 - MM], u0b = xs[bA0 + lA0 + MM];                \
        float u0c = xs[bB0 + lB0 - MM], u0d = xs[bB0 + lB0 + MM];                \
        float u1a = xs[bA1 + lA1 - MM], u1b = xs[bA1 + lA1 + MM];                \
        float u1c = xs[bB1 + lB1 - MM], u1d = xs[bB1 + lB1 + MM];                \
        __half2 p0 = __floats2half2_rn(u0a, u0b), p1 = __floats2half2_rn(u0c, u0d); \
        __half2 q0 = __floats2half2_rn(u1a, u1b), q1 = __floats2half2_rn(u1c, u1d); \
        __half2 r0 = __floats2half2_rn(u0a + u1a, u0b + u1b);                    \
        __half2 r1 = __floats2half2_rn(u0c + u1c, u0d + u1d);                    \
        uint2 P; P.x = *(uint32_t*)&p0; P.y = *(uint32_t*)&p1;                   \
        uint2 Q; Q.x = *(uint32_t*)&q0; Q.y = *(uint32_t*)&q1;                   \
        uint2 Rv; Rv.x = *(uint32_t*)&r0; Rv.y = *(uint32_t*)&r1;                \
        *(uint2*)&g_U[(size_t)NS * P0 + (size_t)n * CO + tb] = P;                \
        *(uint2*)&g_U[(size_t)NS * P1 + (size_t)n * CO + tb] = Q;                \
        *(uint2*)&g_U[(size_t)NS * P2 + (size_t)n * CO + tb] = Rv;               \
    }
    GATH(1, 512, 512, 1024, 1536)
    GATH(2, 384, 2048, 2432, 2816)
    GATH(3, 256, 3200, 3456, 3712)
    GATH(4, 128, 3968, 4096, 4224)
}

// =======================================================================
// Kernel 4: HMMA fp16 GEMM over 13 sub-GEMMs (proven round-13 config)
// =======================================================================
__device__ __forceinline__ uint32_t smem_u32(const void* p) {
    uint32_t a;
    asm("{ .reg .u64 t; cvta.to.shared.u64 t, %1; cvt.u32.u64 %0, t; }" : "=r"(a) : "l"(p));
    return a;
}
#define CP_ASYNC16(dst, src) \
    asm volatile("cp.async.cg.shared.global [%0], [%1], 16;" :: "r"(dst), "l"(src) : "memory")
#define CP_COMMIT() asm volatile("cp.async.commit_group;" ::: "memory")
#define CP_WAIT1()  asm volatile("cp.async.wait_group 1;" ::: "memory")
#define CP_WAIT0()  asm volatile("cp.async.wait_group 0;" ::: "memory")
#define LDSM_X4(r0, r1, r2, r3, addr) \
    asm volatile("ldmatrix.sync.aligned.m8n8.x4.shared.b16 {%0,%1,%2,%3}, [%4];" \
                 : "=r"(r0), "=r"(r1), "=r"(r2), "=r"(r3) : "r"(addr))

__device__ __forceinline__ void hmma16816(float* c, const uint32_t* a, const uint32_t* b) {
    asm volatile(
        "mma.sync.aligned.m16n8k16.row.col.f32.f16.f16.f32 "
        "{%0,%1,%2,%3}, {%4,%5,%6,%7}, {%8,%9}, {%0,%1,%2,%3};"
        : "+f"(c[0]), "+f"(c[1]), "+f"(c[2]), "+f"(c[3])
        : "r"(a[0]), "r"(a[1]), "r"(a[2]), "r"(a[3]), "r"(b[0]), "r"(b[1]));
}

__global__ __launch_bounds__(256) void hmma_gemm_all_kernel() {
    extern __shared__ __align__(1024) char dsm[];
    uint32_t sbase = smem_u32(dsm);

    int tid = threadIdx.x;
    int wid = tid >> 5;
    int lane = tid & 31;

    int id = blockIdx.x;
    int s = 0;
    #pragma unroll
    for (int q = 1; q < 13; q++) if (id >= cg_tileStart[q]) s = q;
    int local = id - cg_tileStart[s];
    int K = cg_Ksub[s];
    int N = cg_Nsub[s];
    int gx = N >> 7;
    int bcolt = local % gx, browt = local / gx;
    int brow = browt << 7, bcol = bcolt << 7;

    const __half* A = g_U + (size_t)NS * cg_Up[s];
    const __half* B = g_W + cg_Wpref[s];
    __half* C = g_Z + (size_t)NS * cg_Zp[s];

    int r = tid >> 1, q2 = tid & 1;
    const char* gA = (const char*)(A + (size_t)(brow + r) * K + q2 * 32);
    const char* gB = (const char*)(B + (size_t)(bcol + r) * K + q2 * 32);
    uint32_t sts[4];
    #pragma unroll
    for (int i = 0; i < 4; i++) {
        uint32_t off = (uint32_t)r * 128u + (uint32_t)(q2 * 4 + i) * 16u;
        sts[i] = off ^ ((off >> 3) & 0x70);
    }

    int wm = wid >> 1, wn = wid & 1;
    uint32_t a_row[2], a_rx[2];
    #pragma unroll
    for (int mt = 0; mt < 2; mt++) {
        int row = wm * 32 + mt * 16 + (lane & 15);
        a_row[mt] = (uint32_t)row * 128u;
        a_rx[mt] = (uint32_t)(row & 7) << 4;
    }
    uint32_t a_cb = ((lane >> 4) & 1) * 16u;
    int nloc = (lane & 7) + ((lane & 16) >> 1);
    uint32_t b_row[4], b_rx[4];
    #pragma unroll
    for (int nt4 = 0; nt4 < 4; nt4++) {
        int nrow = wn * 64 + nt4 * 16 + nloc;
        b_row[nt4] = (uint32_t)nrow * 128u;
        b_rx[nt4] = (uint32_t)(nrow & 7) << 4;
    }
    uint32_t b_cb = ((lane >> 3) & 1) * 16u;

    float acc[2][8][4];
    #pragma unroll
    for (int mt = 0; mt < 2; mt++)
        #pragma unroll
        for (int nt = 0; nt < 8; nt++)
            #pragma unroll
            for (int e = 0; e < 4; e++) acc[mt][nt][e] = 0.f;

    int NC = K >> 6;

    #pragma unroll
    for (int p = 0; p < 2; p++) {
        uint32_t aS = sbase + (uint32_t)p * 32768u;
        uint32_t bS = aS + 16384u;
        const char* Ap = gA + (size_t)p * 128;
        const char* Bp = gB + (size_t)p * 128;
        #pragma unroll
        for (int i = 0; i < 4; i++) {
            CP_ASYNC16(aS + sts[i], Ap + i * 16);
            CP_ASYNC16(bS + sts[i], Bp + i * 16);
        }
        CP_COMMIT();
    }

    for (int c = 0; c < NC; ++c) {
        if (c + 1 < NC) CP_WAIT1(); else CP_WAIT0();
        __syncthreads();
        if (c + 2 < NC) {
            int st = (c + 2) % 3;
            uint32_t aS = sbase + (uint32_t)st * 32768u;
            uint32_t bS = aS + 16384u;
            const char* Ap = gA + (size_t)(c + 2) * 128;
            const char* Bp = gB + (size_t)(c + 2) * 128;
            #pragma unroll
            for (int i = 0; i < 4; i++) {
                CP_ASYNC16(aS + sts[i], Ap + i * 16);
                CP_ASYNC16(bS + sts[i], Bp + i * 16);
            }
            CP_COMMIT();
        }
        int cst = c % 3;
        uint32_t aS = sbase + (uint32_t)cst * 32768u;
        uint32_t bS = aS + 16384u;
        #pragma unroll
        for (int kq = 0; kq < 4; kq++) {
            uint32_t kb = (uint32_t)kq * 32u;
            uint32_t afr[2][4];
            #pragma unroll
            for (int mt = 0; mt < 2; mt++)
                LDSM_X4(afr[mt][0], afr[mt][1], afr[mt][2], afr[mt][3],
                        aS + a_row[mt] + ((a_cb + kb) ^ a_rx[mt]));
            uint32_t bfr[4][4];
            #pragma unroll
            for (int nt4 = 0; nt4 < 4; nt4++)
                LDSM_X4(bfr[nt4][0], bfr[nt4][1], bfr[nt4][2], bfr[nt4][3],
                        bS + b_row[nt4] + ((b_cb + kb) ^ b_rx[nt4]));
            #pragma unroll
            for (int mt = 0; mt < 2; mt++)
                #pragma unroll
                for (int nt = 0; nt < 8; nt++)
                    hmma16816(acc[mt][nt], afr[mt], &bfr[nt >> 1][(nt & 1) * 2]);
        }
    }

    int g2 = lane >> 2, t2 = lane & 3;
    #pragma unroll
    for (int mt = 0; mt < 2; mt++) {
        #pragma unroll
        for (int nt = 0; nt < 8; nt++) {
            int row0 = brow + wm * 32 + mt * 16 + g2;
            int col = bcol + wn * 64 + nt * 8 + t2 * 2;
            __half2 h0 = __floats2half2_rn(acc[mt][nt][0], acc[mt][nt][1]);
            __half2 h1 = __floats2half2_rn(acc[mt][nt][2], acc[mt][nt][3]);
            *(__half2*)(C + (size_t)row0 * N + col) = h0;
            *(__half2*)(C + (size_t)(row0 + 8) * N + col) = h1;
        }
    }
}

// =======================================================================
// Kernel 5: combine fp16 Karatsuba outputs (+bias), rotate in place, write out
//   (8B Z loads: 4 elements per iteration)
// =======================================================================
__global__ __launch_bounds__(256) void scatter_rot_kernel(const float* __restrict__ fc0_b,
                                                          float* __restrict__ out) {
    int n = blockIdx.x;
    __shared__ float pre[DIMX];
    __shared__ float dt[164];

    for (int c = threadIdx.x; c < 164; c += 256) dt[c] = g_DT[(size_t)n * 164 + c];

    // m0: 4 elements per thread, uint2 Z load + float4 bias
    for (int j = threadIdx.x * 4; j < 640; j += 1024) {
        uint2 pk = *(const uint2*)&g_Z[(size_t)n * 640 + j];
        __half2 lo = *(__half2*)&pk.x, hi = *(__half2*)&pk.y;
        float4 bb = *(const float4*)&fc0_b[j];
        int l = j >> 7, k = j & 127;   // k..k+3 same l
        int base = 128*l*l;
        int d = 2*l + 1;
        pre[base + k*d + l]       = __low2float(lo)  + bb.x;
        pre[base + (k+1)*d + l]   = __high2float(lo) + bb.y;
        pre[base + (k+2)*d + l]   = __low2float(hi)  + bb.z;
        pre[base + (k+3)*d + l]   = __high2float(hi) + bb.w;
    }
    // m>=1: 4 elements (2 (l,k) pairs) per iteration, uint2 Z loads
    #define SCAT(MM, CO, P0, P1, P2)                                             \
    for (int tb = threadIdx.x * 4; tb < CO; tb += 1024) {                        \
        uint2 z1 = *(const uint2*)&g_Z[(size_t)NS * P0 + (size_t)n * CO + tb];   \
        uint2 z2 = *(const uint2*)&g_Z[(size_t)NS * P1 + (size_t)n * CO + tb];   \
        uint2 z3 = *(const uint2*)&g_Z[(size_t)NS * P2 + (size_t)n * CO + tb];   \
        __half2 h1a = *(__half2*)&z1.x, h1b = *(__half2*)&z1.y;                  \
        __half2 h2a = *(__half2*)&z2.x, h2b = *(__half2*)&z2.y;                  \
        __half2 h3a = *(__half2*)&z3.x, h3b = *(__half2*)&z3.y;                  \
        float v1a = __low2float(h1a), v1b = __high2float(h1a);                   \
        float v1c = __low2float(h1b), v1d = __high2float(h1b);                   \
        float v2a = __low2float(h2a), v2b = __high2float(h2a);                   \
        float v2c = __low2float(h2b), v2d = __high2float(h2b);                   \
        float v3a = __low2float(h3a), v3b = __high2float(h3a);                   \
        float v3c = __low2float(h3b), v3d = __high2float(h3b);                   \
        int phA = tb >> 1, phB = phA + 1;                                        \
        int pA1 = (CO >> 1) + phA, pB1 = (CO >> 1) + phB;                        \
        int lA0 = MM + (phA >> 7), kA0 = phA & 127;                              \
        int lB0 = MM + (phB >> 7), kB0 = phB & 127;                              \
        int lA1 = MM + (pA1 >> 7), kA1 = pA1 & 127;                              \
        int lB1 = MM + (pB1 >> 7), kB1 = pB1 & 127;                              \
        int bA0 = 128*lA0*lA0 + kA0*(2*lA0 + 1);                                 \
        int bB0 = 128*lB0*lB0 + kB0*(2*lB0 + 1);                                 \
        int bA1 = 128*lA1*lA1 + kA1*(2*lA1 + 1);                                 \
        int bB1 = 128*lB1*lB1 + kB1*(2*lB1 + 1);                                 \
        pre[bA0 + lA0 - MM] = v1a - v2a;                                         \
        pre[bA0 + lA0 + MM] = v1b - v2b;                                         \
        pre[bB0 + lB0 - MM] = v1c - v2c;                                         \
        pre[bB0 + lB0 + MM] = v1d - v2d;                                         \
        pre[bA1 + lA1 - MM] = v3a - v1a - v2a;                                   \
        pre[bA1 + lA1 + MM] = v3b - v1b - v2b;                                   \
        pre[bB1 + lB1 - MM] = v3c - v1c - v2c;                                   \
        pre[bB1 + lB1 + MM] = v3d - v1d - v2d;                                   \
    }
    SCAT(1, 512, 640, 1152, 1664)
    SCAT(2, 384, 2176, 2560, 2944)
    SCAT(3, 256, 3328, 3584, 3840)
    SCAT(4, 128, 4096, 4224, 4352)
    __syncthreads();

    int k = threadIdx.x & 127;
    int h = threadIdx.x >> 7;
    #define ROTO(D, DTO, XO) do {                                            \
        float* pb = pre + XO + k * D;                                        \
        float xv[D];                                                         \
        _Pragma("unroll") for (int j = 0; j < D; j++) xv[j] = pb[j];         \
        _Pragma("unroll") for (int i = 0; i < D; i++) {                      \
            const float* ddp = dt + DTO + i * D;                             \
            float v = 0.f;                                                   \
            _Pragma("unroll") for (int j = 0; j < D; j++) v += ddp[j] * xv[j]; \
            pb[i] = v;                                                       \
        }                                                                    \
    } while (0)
    if (h == 0) { ROTO(3, 0, 128);  ROTO(9, 83, 2048); }
    else        { ROTO(5, 9, 512);  ROTO(7, 34, 1152); }
    __syncthreads();

    float4* orow4 = (float4*)(out + (size_t)n * DIMX);
    for (int c = threadIdx.x; c < DIMX/4; c += 256) orow4[c] = ((const float4*)pre)[c];
}

// =======================================================================
// launch
// =======================================================================
extern "C" void kernel_launch(void* const* d_in, const int* in_sizes, int n_in,
                              void* d_out, int out_size) {
    const float* x     = (const float*)d_in[0];
    const float* R     = (const float*)d_in[1];
    const float* fc0_w = (const float*)d_in[2];
    const float* fc0_b = (const float*)d_in[3];
    const float* w1    = (const float*)d_in[4];
    const float* w2    = (const float*)d_in[5];
    const float* w3    = (const float*)d_in[6];
    const float* w4    = (const float*)d_in[7];
    float* out = (float*)d_out;

    build_J_kernel<<<1, 384>>>();
    rot_gather_buildw_kernel<<<NS + WBLK, 256>>>(x, R, fc0_w, w1, w2, w3, w4);

    cudaFuncSetAttribute(hmma_gemm_all_kernel,
                         cudaFuncAttributeMaxDynamicSharedMemorySize, 98304);
    hmma_gemm_all_kernel<<<4480, 256, 98304>>>();

    scatter_rot_kernel<<<NS, 256>>>(fc0_b, out);
}